// round 1
// baseline (speedup 1.0000x reference)
#include <cuda_runtime.h>
#include <math.h>

#define N_NODES 50000
#define N_EDGES 800000
#define H 128
#define LAYERS 4
#define KE 263          // 2H + 7
#define KN 256          // 2H
#define BM 128
#define BK 8
#define AP 132          // acts pitch (padded, keeps 16B alignment)

// Scratch (device globals; allocation in kernel_launch is forbidden)
__device__ float g_h[N_NODES * H];
__device__ float g_agg[N_NODES * H];
__device__ float g_ea[N_EDGES * 4];

__device__ __forceinline__ void red_add_f4(float* p, float a, float b, float c, float d) {
    asm volatile("red.global.add.v4.f32 [%0], {%1,%2,%3,%4};"
                 :: "l"(p), "f"(a), "f"(b), "f"(c), "f"(d) : "memory");
}

// ---------------------------------------------------------------- embed: h = x @ W_in + b_in
__global__ void embed_kernel(const float* __restrict__ x,
                             const float* __restrict__ W,
                             const float* __restrict__ b) {
    int gid = blockIdx.x * blockDim.x + threadIdx.x;
    if (gid >= N_NODES * H) return;
    int i = gid >> 7;
    int j = gid & (H - 1);
    const float* xr = x + i * 16;
    float acc = b[j];
#pragma unroll
    for (int k = 0; k < 16; k++) acc += xr[k] * W[k * H + j];
    g_h[gid] = acc;
}

// ---------------------------------------------------------------- edge_attr = [rel_pos, dist]
__global__ void ea_kernel(const float* __restrict__ pos,
                          const int* __restrict__ rowIdx,
                          const int* __restrict__ colIdx) {
    int e = blockIdx.x * blockDim.x + threadIdx.x;
    if (e >= N_EDGES) return;
    int r = rowIdx[e], c = colIdx[e];
    float dx = pos[c * 3 + 0] - pos[r * 3 + 0];
    float dy = pos[c * 3 + 1] - pos[r * 3 + 1];
    float dz = pos[c * 3 + 2] - pos[r * 3 + 2];
    float d = sqrtf(dx * dx + dy * dy + dz * dz);
    *(float4*)&g_ea[e * 4] = make_float4(dx, dy, dz, d);
}

// ---------------------------------------------------------------- zero agg
__global__ void zero_agg_kernel() {
    int gid = blockIdx.x * blockDim.x + threadIdx.x;
    ((float4*)g_agg)[gid] = make_float4(0.f, 0.f, 0.f, 0.f);
}

// ---------------------------------------------------------------- fused edge MLP + scatter-add
// smem layout (floats): [0..255] int indices (col,row), As[BM*BK], Bs[BK*H], acts[BM*AP]
__global__ __launch_bounds__(256, 2)
void edge_kernel(const float* __restrict__ We1, const float* __restrict__ be1,
                 const float* __restrict__ We2, const float* __restrict__ be2,
                 const float* __restrict__ We3, const float* __restrict__ be3,
                 const int* __restrict__ rowIdx, const int* __restrict__ colIdx) {
    extern __shared__ float smem[];
    int* s_col = (int*)smem;
    int* s_row = s_col + BM;
    float* As = smem + 256;
    float* Bs = As + BM * BK;
    float* acts = Bs + BK * H;

    int tid = threadIdx.x;
    int eb = blockIdx.x * BM;

    if (tid < 128) s_col[tid] = colIdx[eb + tid];
    else           s_row[tid - 128] = rowIdx[eb + tid - 128];
    __syncthreads();

    int tx = tid & 15, ty = tid >> 4;
    int le = tid >> 1;            // A-load: edge 0..127
    int lk = (tid & 1) * 4;       // A-load: k offset 0/4
    int wk = tid >> 5;            // B-load: k row 0..7
    int wn = (tid & 31) * 4;      // B-load: n offset

    float c[8][8];
#pragma unroll
    for (int i = 0; i < 8; i++)
#pragma unroll
        for (int j = 0; j < 8; j++) c[i][j] = 0.f;

    // ---- GEMM1: m1 = relu([h[col] | h[row] | ea] @ We1 + be1), K = 263
    for (int kk = 0; kk < KE; kk += BK) {
        float4 av;
        if (kk < 128) {
            av = *(const float4*)&g_h[s_col[le] * H + kk + lk];
        } else if (kk < 256) {
            av = *(const float4*)&g_h[s_row[le] * H + (kk - 128) + lk];
        } else {
            if (lk == 0) {
                av = *(const float4*)&g_ea[(eb + le) * 4];
            } else {
                int ci = s_col[le] * H, ri = s_row[le] * H;
                av.x = g_h[ci + 3] - g_h[ri + 3];
                av.y = g_h[ci + 4] - g_h[ri + 4];
                av.z = g_h[ci + 5] - g_h[ri + 5];
                av.w = 0.f;
            }
        }
        *(float4*)&As[le * BK + lk] = av;

        float4 bv = make_float4(0.f, 0.f, 0.f, 0.f);
        int krow = kk + wk;
        if (krow < KE) bv = *(const float4*)&We1[krow * H + wn];
        *(float4*)&Bs[wk * H + wn] = bv;
        __syncthreads();
#pragma unroll
        for (int k = 0; k < BK; k++) {
            float a[8];
#pragma unroll
            for (int i = 0; i < 8; i++) a[i] = As[(ty * 8 + i) * BK + k];
            float4 b0 = *(float4*)&Bs[k * H + tx * 8];
            float4 b1 = *(float4*)&Bs[k * H + tx * 8 + 4];
            float bb[8] = {b0.x, b0.y, b0.z, b0.w, b1.x, b1.y, b1.z, b1.w};
#pragma unroll
            for (int i = 0; i < 8; i++)
#pragma unroll
                for (int j = 0; j < 8; j++) c[i][j] += a[i] * bb[j];
        }
        __syncthreads();
    }
    {
        float4 t0 = *(const float4*)&be1[tx * 8];
        float4 t1 = *(const float4*)&be1[tx * 8 + 4];
        float bias[8] = {t0.x, t0.y, t0.z, t0.w, t1.x, t1.y, t1.z, t1.w};
#pragma unroll
        for (int i = 0; i < 8; i++) {
            float4 v0, v1;
            v0.x = fmaxf(c[i][0] + bias[0], 0.f); v0.y = fmaxf(c[i][1] + bias[1], 0.f);
            v0.z = fmaxf(c[i][2] + bias[2], 0.f); v0.w = fmaxf(c[i][3] + bias[3], 0.f);
            v1.x = fmaxf(c[i][4] + bias[4], 0.f); v1.y = fmaxf(c[i][5] + bias[5], 0.f);
            v1.z = fmaxf(c[i][6] + bias[6], 0.f); v1.w = fmaxf(c[i][7] + bias[7], 0.f);
            *(float4*)&acts[(ty * 8 + i) * AP + tx * 8] = v0;
            *(float4*)&acts[(ty * 8 + i) * AP + tx * 8 + 4] = v1;
        }
    }
    __syncthreads();

    // ---- GEMM2: m2 = relu(m1 @ We2 + be2), K = 128
#pragma unroll
    for (int i = 0; i < 8; i++)
#pragma unroll
        for (int j = 0; j < 8; j++) c[i][j] = 0.f;
    for (int kk = 0; kk < H; kk += BK) {
        *(float4*)&Bs[wk * H + wn] = *(const float4*)&We2[(kk + wk) * H + wn];
        __syncthreads();
#pragma unroll
        for (int k = 0; k < BK; k++) {
            float a[8];
#pragma unroll
            for (int i = 0; i < 8; i++) a[i] = acts[(ty * 8 + i) * AP + kk + k];
            float4 b0 = *(float4*)&Bs[k * H + tx * 8];
            float4 b1 = *(float4*)&Bs[k * H + tx * 8 + 4];
            float bb[8] = {b0.x, b0.y, b0.z, b0.w, b1.x, b1.y, b1.z, b1.w};
#pragma unroll
            for (int i = 0; i < 8; i++)
#pragma unroll
                for (int j = 0; j < 8; j++) c[i][j] += a[i] * bb[j];
        }
        __syncthreads();
    }
    {
        float4 t0 = *(const float4*)&be2[tx * 8];
        float4 t1 = *(const float4*)&be2[tx * 8 + 4];
        float bias[8] = {t0.x, t0.y, t0.z, t0.w, t1.x, t1.y, t1.z, t1.w};
        float m2[8][8];
#pragma unroll
        for (int i = 0; i < 8; i++)
#pragma unroll
            for (int j = 0; j < 8; j++) m2[i][j] = fmaxf(c[i][j] + bias[j], 0.f);
        __syncthreads();   // all reads of acts done before overwrite
#pragma unroll
        for (int i = 0; i < 8; i++) {
            *(float4*)&acts[(ty * 8 + i) * AP + tx * 8]     = make_float4(m2[i][0], m2[i][1], m2[i][2], m2[i][3]);
            *(float4*)&acts[(ty * 8 + i) * AP + tx * 8 + 4] = make_float4(m2[i][4], m2[i][5], m2[i][6], m2[i][7]);
        }
    }
    __syncthreads();

    // ---- GEMM3: m3 = m2 @ We3 + be3, K = 128, then scatter-add to agg[col]
#pragma unroll
    for (int i = 0; i < 8; i++)
#pragma unroll
        for (int j = 0; j < 8; j++) c[i][j] = 0.f;
    for (int kk = 0; kk < H; kk += BK) {
        *(float4*)&Bs[wk * H + wn] = *(const float4*)&We3[(kk + wk) * H + wn];
        __syncthreads();
#pragma unroll
        for (int k = 0; k < BK; k++) {
            float a[8];
#pragma unroll
            for (int i = 0; i < 8; i++) a[i] = acts[(ty * 8 + i) * AP + kk + k];
            float4 b0 = *(float4*)&Bs[k * H + tx * 8];
            float4 b1 = *(float4*)&Bs[k * H + tx * 8 + 4];
            float bb[8] = {b0.x, b0.y, b0.z, b0.w, b1.x, b1.y, b1.z, b1.w};
#pragma unroll
            for (int i = 0; i < 8; i++)
#pragma unroll
                for (int j = 0; j < 8; j++) c[i][j] += a[i] * bb[j];
        }
        __syncthreads();
    }
    {
        float4 t0 = *(const float4*)&be3[tx * 8];
        float4 t1 = *(const float4*)&be3[tx * 8 + 4];
        float bias[8] = {t0.x, t0.y, t0.z, t0.w, t1.x, t1.y, t1.z, t1.w};
#pragma unroll
        for (int i = 0; i < 8; i++) {
            int tgt = s_col[ty * 8 + i];
            float* base = &g_agg[tgt * H + tx * 8];
            red_add_f4(base,     c[i][0] + bias[0], c[i][1] + bias[1], c[i][2] + bias[2], c[i][3] + bias[3]);
            red_add_f4(base + 4, c[i][4] + bias[4], c[i][5] + bias[5], c[i][6] + bias[6], c[i][7] + bias[7]);
        }
    }
}

// ---------------------------------------------------------------- fused node MLP + residual + LN
// smem: As[BM*BK], Bs[BK*H], acts[BM*AP]
__global__ __launch_bounds__(256, 2)
void node_kernel(const float* __restrict__ Wn1, const float* __restrict__ bn1,
                 const float* __restrict__ Wn2, const float* __restrict__ bn2,
                 const float* __restrict__ Wn3, const float* __restrict__ bn3,
                 const float* __restrict__ lng, const float* __restrict__ lnb,
                 float* __restrict__ out) {
    extern __shared__ float smem[];
    float* As = smem;
    float* Bs = As + BM * BK;
    float* acts = Bs + BK * H;

    int tid = threadIdx.x;
    int nb = blockIdx.x * BM;
    int tx = tid & 15, ty = tid >> 4;
    int le = tid >> 1;
    int lk = (tid & 1) * 4;
    int wk = tid >> 5;
    int wn = (tid & 31) * 4;

    float c[8][8];
#pragma unroll
    for (int i = 0; i < 8; i++)
#pragma unroll
        for (int j = 0; j < 8; j++) c[i][j] = 0.f;

    // ---- GEMM1: u1 = relu([h | agg] @ Wn1 + bn1), K = 256
    for (int kk = 0; kk < KN; kk += BK) {
        int node = nb + le;
        float4 av = make_float4(0.f, 0.f, 0.f, 0.f);
        if (node < N_NODES) {
            if (kk < 128) av = *(const float4*)&g_h[node * H + kk + lk];
            else          av = *(const float4*)&g_agg[node * H + (kk - 128) + lk];
        }
        *(float4*)&As[le * BK + lk] = av;
        *(float4*)&Bs[wk * H + wn] = *(const float4*)&Wn1[(kk + wk) * H + wn];
        __syncthreads();
#pragma unroll
        for (int k = 0; k < BK; k++) {
            float a[8];
#pragma unroll
            for (int i = 0; i < 8; i++) a[i] = As[(ty * 8 + i) * BK + k];
            float4 b0 = *(float4*)&Bs[k * H + tx * 8];
            float4 b1 = *(float4*)&Bs[k * H + tx * 8 + 4];
            float bb[8] = {b0.x, b0.y, b0.z, b0.w, b1.x, b1.y, b1.z, b1.w};
#pragma unroll
            for (int i = 0; i < 8; i++)
#pragma unroll
                for (int j = 0; j < 8; j++) c[i][j] += a[i] * bb[j];
        }
        __syncthreads();
    }
    {
        float4 t0 = *(const float4*)&bn1[tx * 8];
        float4 t1 = *(const float4*)&bn1[tx * 8 + 4];
        float bias[8] = {t0.x, t0.y, t0.z, t0.w, t1.x, t1.y, t1.z, t1.w};
#pragma unroll
        for (int i = 0; i < 8; i++) {
            float4 v0, v1;
            v0.x = fmaxf(c[i][0] + bias[0], 0.f); v0.y = fmaxf(c[i][1] + bias[1], 0.f);
            v0.z = fmaxf(c[i][2] + bias[2], 0.f); v0.w = fmaxf(c[i][3] + bias[3], 0.f);
            v1.x = fmaxf(c[i][4] + bias[4], 0.f); v1.y = fmaxf(c[i][5] + bias[5], 0.f);
            v1.z = fmaxf(c[i][6] + bias[6], 0.f); v1.w = fmaxf(c[i][7] + bias[7], 0.f);
            *(float4*)&acts[(ty * 8 + i) * AP + tx * 8] = v0;
            *(float4*)&acts[(ty * 8 + i) * AP + tx * 8 + 4] = v1;
        }
    }
    __syncthreads();

    // ---- GEMM2: relu(u1 @ Wn2 + bn2)
#pragma unroll
    for (int i = 0; i < 8; i++)
#pragma unroll
        for (int j = 0; j < 8; j++) c[i][j] = 0.f;
    for (int kk = 0; kk < H; kk += BK) {
        *(float4*)&Bs[wk * H + wn] = *(const float4*)&Wn2[(kk + wk) * H + wn];
        __syncthreads();
#pragma unroll
        for (int k = 0; k < BK; k++) {
            float a[8];
#pragma unroll
            for (int i = 0; i < 8; i++) a[i] = acts[(ty * 8 + i) * AP + kk + k];
            float4 b0 = *(float4*)&Bs[k * H + tx * 8];
            float4 b1 = *(float4*)&Bs[k * H + tx * 8 + 4];
            float bb[8] = {b0.x, b0.y, b0.z, b0.w, b1.x, b1.y, b1.z, b1.w};
#pragma unroll
            for (int i = 0; i < 8; i++)
#pragma unroll
                for (int j = 0; j < 8; j++) c[i][j] += a[i] * bb[j];
        }
        __syncthreads();
    }
    {
        float4 t0 = *(const float4*)&bn2[tx * 8];
        float4 t1 = *(const float4*)&bn2[tx * 8 + 4];
        float bias[8] = {t0.x, t0.y, t0.z, t0.w, t1.x, t1.y, t1.z, t1.w};
        float m2[8][8];
#pragma unroll
        for (int i = 0; i < 8; i++)
#pragma unroll
            for (int j = 0; j < 8; j++) m2[i][j] = fmaxf(c[i][j] + bias[j], 0.f);
        __syncthreads();
#pragma unroll
        for (int i = 0; i < 8; i++) {
            *(float4*)&acts[(ty * 8 + i) * AP + tx * 8]     = make_float4(m2[i][0], m2[i][1], m2[i][2], m2[i][3]);
            *(float4*)&acts[(ty * 8 + i) * AP + tx * 8 + 4] = make_float4(m2[i][4], m2[i][5], m2[i][6], m2[i][7]);
        }
    }
    __syncthreads();

    // ---- GEMM3: u = u2 @ Wn3 + bn3; pre = h + u
#pragma unroll
    for (int i = 0; i < 8; i++)
#pragma unroll
        for (int j = 0; j < 8; j++) c[i][j] = 0.f;
    for (int kk = 0; kk < H; kk += BK) {
        *(float4*)&Bs[wk * H + wn] = *(const float4*)&Wn3[(kk + wk) * H + wn];
        __syncthreads();
#pragma unroll
        for (int k = 0; k < BK; k++) {
            float a[8];
#pragma unroll
            for (int i = 0; i < 8; i++) a[i] = acts[(ty * 8 + i) * AP + kk + k];
            float4 b0 = *(float4*)&Bs[k * H + tx * 8];
            float4 b1 = *(float4*)&Bs[k * H + tx * 8 + 4];
            float bb[8] = {b0.x, b0.y, b0.z, b0.w, b1.x, b1.y, b1.z, b1.w};
#pragma unroll
            for (int i = 0; i < 8; i++)
#pragma unroll
                for (int j = 0; j < 8; j++) c[i][j] += a[i] * bb[j];
        }
        __syncthreads();
    }
    {
        float4 t0 = *(const float4*)&bn3[tx * 8];
        float4 t1 = *(const float4*)&bn3[tx * 8 + 4];
        float bias[8] = {t0.x, t0.y, t0.z, t0.w, t1.x, t1.y, t1.z, t1.w};
#pragma unroll
        for (int i = 0; i < 8; i++) {
            int node = nb + ty * 8 + i;
            float4 h0 = make_float4(0.f, 0.f, 0.f, 0.f), h1 = make_float4(0.f, 0.f, 0.f, 0.f);
            if (node < N_NODES) {
                h0 = *(const float4*)&g_h[node * H + tx * 8];
                h1 = *(const float4*)&g_h[node * H + tx * 8 + 4];
            }
            *(float4*)&acts[(ty * 8 + i) * AP + tx * 8] =
                make_float4(h0.x + c[i][0] + bias[0], h0.y + c[i][1] + bias[1],
                            h0.z + c[i][2] + bias[2], h0.w + c[i][3] + bias[3]);
            *(float4*)&acts[(ty * 8 + i) * AP + tx * 8 + 4] =
                make_float4(h1.x + c[i][4] + bias[4], h1.y + c[i][5] + bias[5],
                            h1.z + c[i][6] + bias[6], h1.w + c[i][7] + bias[7]);
        }
    }
    __syncthreads();

    // ---- LayerNorm per row, write output
    {
        int lane = tid & 31, warp = tid >> 5;
        for (int r = warp * 16; r < warp * 16 + 16; r++) {
            int node = nb + r;
            float v0 = acts[r * AP + lane];
            float v1 = acts[r * AP + lane + 32];
            float v2 = acts[r * AP + lane + 64];
            float v3 = acts[r * AP + lane + 96];
            float s = v0 + v1 + v2 + v3;
            float q = v0 * v0 + v1 * v1 + v2 * v2 + v3 * v3;
#pragma unroll
            for (int off = 16; off > 0; off >>= 1) {
                s += __shfl_xor_sync(0xffffffffu, s, off);
                q += __shfl_xor_sync(0xffffffffu, q, off);
            }
            float mean = s * (1.f / 128.f);
            float var = q * (1.f / 128.f) - mean * mean;
            float rstd = rsqrtf(var + 1e-5f);
            if (node < N_NODES) {
                out[node * H + lane]      = (v0 - mean) * rstd * lng[lane]      + lnb[lane];
                out[node * H + lane + 32] = (v1 - mean) * rstd * lng[lane + 32] + lnb[lane + 32];
                out[node * H + lane + 64] = (v2 - mean) * rstd * lng[lane + 64] + lnb[lane + 64];
                out[node * H + lane + 96] = (v3 - mean) * rstd * lng[lane + 96] + lnb[lane + 96];
            }
        }
    }
}

// ----------------------------------------------------------------
extern "C" void kernel_launch(void* const* d_in, const int* in_sizes, int n_in,
                              void* d_out, int out_size) {
    const float* x    = (const float*)d_in[0];
    const float* pos  = (const float*)d_in[1];
    const int*   ei   = (const int*)d_in[2];
    const float* W_in = (const float*)d_in[3];
    const float* b_in = (const float*)d_in[4];
    const float* We1  = (const float*)d_in[5];
    const float* be1  = (const float*)d_in[6];
    const float* We2  = (const float*)d_in[7];
    const float* be2  = (const float*)d_in[8];
    const float* We3  = (const float*)d_in[9];
    const float* be3  = (const float*)d_in[10];
    const float* Wn1  = (const float*)d_in[11];
    const float* bn1  = (const float*)d_in[12];
    const float* Wn2  = (const float*)d_in[13];
    const float* bn2  = (const float*)d_in[14];
    const float* Wn3  = (const float*)d_in[15];
    const float* bn3  = (const float*)d_in[16];
    const float* ln_g = (const float*)d_in[17];
    const float* ln_b = (const float*)d_in[18];

    const int* rowIdx = ei;
    const int* colIdx = ei + N_EDGES;

    size_t smem_edge = (size_t)(256 + BM * BK + BK * H + BM * AP) * sizeof(float);
    size_t smem_node = (size_t)(BM * BK + BK * H + BM * AP) * sizeof(float);
    cudaFuncSetAttribute(edge_kernel, cudaFuncAttributeMaxDynamicSharedMemorySize, (int)smem_edge);
    cudaFuncSetAttribute(node_kernel, cudaFuncAttributeMaxDynamicSharedMemorySize, (int)smem_node);

    float* hptr = nullptr;
    cudaGetSymbolAddress((void**)&hptr, g_h);

    embed_kernel<<<(N_NODES * H + 255) / 256, 256>>>(x, W_in, b_in);
    ea_kernel<<<(N_EDGES + 255) / 256, 256>>>(pos, rowIdx, colIdx);

    int edge_blocks = N_EDGES / BM;                 // 6250
    int node_blocks = (N_NODES + BM - 1) / BM;      // 391
    int zero_blocks = (N_NODES * H / 4) / 256;      // 6250

    for (int l = 0; l < LAYERS; l++) {
        zero_agg_kernel<<<zero_blocks, 256>>>();
        edge_kernel<<<edge_blocks, 256, smem_edge>>>(
            We1 + (size_t)l * KE * H, be1 + l * H,
            We2 + (size_t)l * H * H,  be2 + l * H,
            We3 + (size_t)l * H * H,  be3 + l * H,
            rowIdx, colIdx);
        float* outp = (l == LAYERS - 1) ? (float*)d_out : hptr;
        node_kernel<<<node_blocks, 256, smem_node>>>(
            Wn1 + (size_t)l * KN * H, bn1 + l * H,
            Wn2 + (size_t)l * H * H,  bn2 + l * H,
            Wn3 + (size_t)l * H * H,  bn3 + l * H,
            ln_g + l * H, ln_b + l * H, outp);
    }
}

// round 2
// speedup vs baseline: 2.2179x; 2.2179x over previous
#include <cuda_runtime.h>
#include <math.h>

#define N_NODES 50000
#define N_EDGES 800000
#define H 128
#define LAYERS 4
#define KE 263
#define KN 256
#define BM 128
#define BK 8
#define AP 132

#define APAD1 36     // GEMM1 A staging stride (words)
#define APACT 132    // activation tile stride (words)
#define BPAD  136    // B tile stride (words)

// Scratch (device globals; allocation in kernel_launch is forbidden)
__device__ float g_h[N_NODES * H];
__device__ float g_agg[N_NODES * H];
__device__ float g_ea[N_EDGES * 4];

__device__ __forceinline__ void red_add_f2(float* p, float a, float b) {
    asm volatile("red.global.add.v2.f32 [%0], {%1,%2};"
                 :: "l"(p), "f"(a), "f"(b) : "memory");
}

__device__ __forceinline__ unsigned f2tf(float f) {
    unsigned u;
    asm("cvt.rna.tf32.f32 %0, %1;" : "=r"(u) : "f"(f));
    return u;
}

__device__ __forceinline__ void mma_tf32(float d[4], const unsigned a[4], const unsigned b[2]) {
    asm volatile("mma.sync.aligned.m16n8k8.row.col.f32.tf32.tf32.f32 "
                 "{%0,%1,%2,%3}, {%4,%5,%6,%7}, {%8,%9}, {%0,%1,%2,%3};"
                 : "+f"(d[0]), "+f"(d[1]), "+f"(d[2]), "+f"(d[3])
                 : "r"(a[0]), "r"(a[1]), "r"(a[2]), "r"(a[3]), "r"(b[0]), "r"(b[1]));
}

// ---------------------------------------------------------------- embed
__global__ void embed_kernel(const float* __restrict__ x,
                             const float* __restrict__ W,
                             const float* __restrict__ b) {
    int gid = blockIdx.x * blockDim.x + threadIdx.x;
    if (gid >= N_NODES * H) return;
    int i = gid >> 7;
    int j = gid & (H - 1);
    const float* xr = x + i * 16;
    float acc = b[j];
#pragma unroll
    for (int k = 0; k < 16; k++) acc += xr[k] * W[k * H + j];
    g_h[gid] = acc;
}

// ---------------------------------------------------------------- edge_attr
__global__ void ea_kernel(const float* __restrict__ pos,
                          const int* __restrict__ rowIdx,
                          const int* __restrict__ colIdx) {
    int e = blockIdx.x * blockDim.x + threadIdx.x;
    if (e >= N_EDGES) return;
    int r = rowIdx[e], c = colIdx[e];
    float dx = pos[c * 3 + 0] - pos[r * 3 + 0];
    float dy = pos[c * 3 + 1] - pos[r * 3 + 1];
    float dz = pos[c * 3 + 2] - pos[r * 3 + 2];
    float d = sqrtf(dx * dx + dy * dy + dz * dz);
    *(float4*)&g_ea[e * 4] = make_float4(dx, dy, dz, d);
}

// ---------------------------------------------------------------- zero agg
__global__ void zero_agg_kernel() {
    int gid = blockIdx.x * blockDim.x + threadIdx.x;
    ((float4*)g_agg)[gid] = make_float4(0.f, 0.f, 0.f, 0.f);
}

// ---------------------------------------------------------------- fused edge MLP (tf32 mma) + scatter
// smem (words): s_col[128], s_row[128], sA[128*132 (aliased GEMM1 staging @stride36)], sB[32*136]
__global__ __launch_bounds__(256, 2)
void edge_kernel(const float* __restrict__ We1, const float* __restrict__ be1,
                 const float* __restrict__ We2, const float* __restrict__ be2,
                 const float* __restrict__ We3, const float* __restrict__ be3,
                 const int* __restrict__ rowIdx, const int* __restrict__ colIdx) {
    extern __shared__ unsigned smem_u[];
    int* s_col = (int*)smem_u;
    int* s_row = s_col + 128;
    unsigned* sA = smem_u + 256;
    unsigned* sB = sA + 128 * APACT;

    int tid = threadIdx.x;
    int eb = blockIdx.x * BM;

    if (tid < 128) s_col[tid] = colIdx[eb + tid];
    else           s_row[tid - 128] = rowIdx[eb + tid - 128];
    __syncthreads();

    int warp = tid >> 5, lane = tid & 31;
    int lr = lane >> 2, lc = lane & 3;
    int wm = (warp & 1) * 64;
    int wn = (warp >> 1) * 32;

    int r = tid >> 1, half = tid & 1;         // A staging: row, col-half
    int br = tid >> 3, bs = (tid & 7) * 16;   // B staging: row, col segment

    float d[4][4][4];
#pragma unroll
    for (int mt = 0; mt < 4; mt++)
#pragma unroll
        for (int nt = 0; nt < 4; nt++)
#pragma unroll
            for (int i = 0; i < 4; i++) d[mt][nt][i] = 0.f;

    // ================= GEMM1: [h[col] | h[row] | ea7] @ We1, K = 264 (263 + pad)
    for (int ch = 0; ch < 9; ch++) {
        int kk = ch * 32;
        // ---- stage A chunk (tf32), stride APAD1
        if (ch < 8) {
            int node = (kk < 128) ? s_col[r] : s_row[r];
            int kbase = (kk < 128) ? kk : (kk - 128);
            const float4* p = (const float4*)&g_h[node * H + kbase + half * 16];
#pragma unroll
            for (int j = 0; j < 4; j++) {
                float4 v = p[j];
                unsigned* dst = &sA[r * APAD1 + half * 16 + j * 4];
                dst[0] = f2tf(v.x); dst[1] = f2tf(v.y);
                dst[2] = f2tf(v.z); dst[3] = f2tf(v.w);
            }
        } else if (half == 0) {
            float4 ea = *(const float4*)&g_ea[(eb + r) * 4];
            int ci = s_col[r] * H, ri = s_row[r] * H;
            unsigned* dst = &sA[r * APAD1];
            dst[0] = f2tf(ea.x); dst[1] = f2tf(ea.y);
            dst[2] = f2tf(ea.z); dst[3] = f2tf(ea.w);
            dst[4] = f2tf(g_h[ci + 3] - g_h[ri + 3]);
            dst[5] = f2tf(g_h[ci + 4] - g_h[ri + 4]);
            dst[6] = f2tf(g_h[ci + 5] - g_h[ri + 5]);
            dst[7] = 0u;
        }
        // ---- stage B chunk from We1
        if (ch < 8 || br < 8) {
            bool ok = (kk + br) < KE;
            const float4* wp = (const float4*)&We1[(size_t)(kk + br) * H + bs];
#pragma unroll
            for (int j = 0; j < 4; j++) {
                float4 v = ok ? wp[j] : make_float4(0.f, 0.f, 0.f, 0.f);
                unsigned* dst = &sB[br * BPAD + bs + j * 4];
                dst[0] = f2tf(v.x); dst[1] = f2tf(v.y);
                dst[2] = f2tf(v.z); dst[3] = f2tf(v.w);
            }
        }
        __syncthreads();
        int nk8 = (ch < 8) ? 4 : 1;
        for (int k8 = 0; k8 < nk8; k8++) {
            int k0 = k8 * 8;
            unsigned bf[4][2];
#pragma unroll
            for (int nt = 0; nt < 4; nt++) {
                int n = wn + nt * 8 + lr;
                bf[nt][0] = sB[(k0 + lc) * BPAD + n];
                bf[nt][1] = sB[(k0 + lc + 4) * BPAD + n];
            }
#pragma unroll
            for (int mt = 0; mt < 4; mt++) {
                int m0 = wm + mt * 16 + lr;
                unsigned af[4];
                af[0] = sA[m0 * APAD1 + k0 + lc];
                af[1] = sA[(m0 + 8) * APAD1 + k0 + lc];
                af[2] = sA[m0 * APAD1 + k0 + lc + 4];
                af[3] = sA[(m0 + 8) * APAD1 + k0 + lc + 4];
#pragma unroll
                for (int nt = 0; nt < 4; nt++) mma_tf32(d[mt][nt], af, bf[nt]);
            }
        }
        __syncthreads();
    }
    // epilogue1: bias + relu -> acts (tf32, stride APACT)
#pragma unroll
    for (int mt = 0; mt < 4; mt++)
#pragma unroll
        for (int nt = 0; nt < 4; nt++) {
            int row = wm + mt * 16 + lr;
            int col = wn + nt * 8 + 2 * lc;
            float2 bv = *(const float2*)&be1[col];
            sA[row * APACT + col]           = f2tf(fmaxf(d[mt][nt][0] + bv.x, 0.f));
            sA[row * APACT + col + 1]       = f2tf(fmaxf(d[mt][nt][1] + bv.y, 0.f));
            sA[(row + 8) * APACT + col]     = f2tf(fmaxf(d[mt][nt][2] + bv.x, 0.f));
            sA[(row + 8) * APACT + col + 1] = f2tf(fmaxf(d[mt][nt][3] + bv.y, 0.f));
        }
    __syncthreads();

    // ================= GEMM2: relu(acts @ We2 + be2), K = 128
#pragma unroll
    for (int mt = 0; mt < 4; mt++)
#pragma unroll
        for (int nt = 0; nt < 4; nt++)
#pragma unroll
            for (int i = 0; i < 4; i++) d[mt][nt][i] = 0.f;
    for (int ch = 0; ch < 4; ch++) {
        int kk = ch * 32;
        const float4* wp = (const float4*)&We2[(size_t)(kk + br) * H + bs];
#pragma unroll
        for (int j = 0; j < 4; j++) {
            float4 v = wp[j];
            unsigned* dst = &sB[br * BPAD + bs + j * 4];
            dst[0] = f2tf(v.x); dst[1] = f2tf(v.y);
            dst[2] = f2tf(v.z); dst[3] = f2tf(v.w);
        }
        __syncthreads();
#pragma unroll
        for (int k8 = 0; k8 < 4; k8++) {
            int k0 = k8 * 8;
            unsigned bf[4][2];
#pragma unroll
            for (int nt = 0; nt < 4; nt++) {
                int n = wn + nt * 8 + lr;
                bf[nt][0] = sB[(k0 + lc) * BPAD + n];
                bf[nt][1] = sB[(k0 + lc + 4) * BPAD + n];
            }
#pragma unroll
            for (int mt = 0; mt < 4; mt++) {
                int m0 = wm + mt * 16 + lr;
                unsigned af[4];
                af[0] = sA[m0 * APACT + kk + k0 + lc];
                af[1] = sA[(m0 + 8) * APACT + kk + k0 + lc];
                af[2] = sA[m0 * APACT + kk + k0 + lc + 4];
                af[3] = sA[(m0 + 8) * APACT + kk + k0 + lc + 4];
#pragma unroll
                for (int nt = 0; nt < 4; nt++) mma_tf32(d[mt][nt], af, bf[nt]);
            }
        }
        __syncthreads();
    }
    // epilogue2 (in-place rewrite of acts after barrier)
    {
        unsigned tmp[4][4][2][2];
#pragma unroll
        for (int mt = 0; mt < 4; mt++)
#pragma unroll
            for (int nt = 0; nt < 4; nt++) {
                int col = wn + nt * 8 + 2 * lc;
                float2 bv = *(const float2*)&be2[col];
                tmp[mt][nt][0][0] = f2tf(fmaxf(d[mt][nt][0] + bv.x, 0.f));
                tmp[mt][nt][0][1] = f2tf(fmaxf(d[mt][nt][1] + bv.y, 0.f));
                tmp[mt][nt][1][0] = f2tf(fmaxf(d[mt][nt][2] + bv.x, 0.f));
                tmp[mt][nt][1][1] = f2tf(fmaxf(d[mt][nt][3] + bv.y, 0.f));
            }
#pragma unroll
        for (int mt = 0; mt < 4; mt++)
#pragma unroll
            for (int nt = 0; nt < 4; nt++) {
                int row = wm + mt * 16 + lr;
                int col = wn + nt * 8 + 2 * lc;
                sA[row * APACT + col]           = tmp[mt][nt][0][0];
                sA[row * APACT + col + 1]       = tmp[mt][nt][0][1];
                sA[(row + 8) * APACT + col]     = tmp[mt][nt][1][0];
                sA[(row + 8) * APACT + col + 1] = tmp[mt][nt][1][1];
            }
    }
    __syncthreads();

    // ================= GEMM3: acts @ We3 + be3, K = 128, scatter-add
#pragma unroll
    for (int mt = 0; mt < 4; mt++)
#pragma unroll
        for (int nt = 0; nt < 4; nt++)
#pragma unroll
            for (int i = 0; i < 4; i++) d[mt][nt][i] = 0.f;
    for (int ch = 0; ch < 4; ch++) {
        int kk = ch * 32;
        const float4* wp = (const float4*)&We3[(size_t)(kk + br) * H + bs];
#pragma unroll
        for (int j = 0; j < 4; j++) {
            float4 v = wp[j];
            unsigned* dst = &sB[br * BPAD + bs + j * 4];
            dst[0] = f2tf(v.x); dst[1] = f2tf(v.y);
            dst[2] = f2tf(v.z); dst[3] = f2tf(v.w);
        }
        __syncthreads();
#pragma unroll
        for (int k8 = 0; k8 < 4; k8++) {
            int k0 = k8 * 8;
            unsigned bf[4][2];
#pragma unroll
            for (int nt = 0; nt < 4; nt++) {
                int n = wn + nt * 8 + lr;
                bf[nt][0] = sB[(k0 + lc) * BPAD + n];
                bf[nt][1] = sB[(k0 + lc + 4) * BPAD + n];
            }
#pragma unroll
            for (int mt = 0; mt < 4; mt++) {
                int m0 = wm + mt * 16 + lr;
                unsigned af[4];
                af[0] = sA[m0 * APACT + kk + k0 + lc];
                af[1] = sA[(m0 + 8) * APACT + kk + k0 + lc];
                af[2] = sA[m0 * APACT + kk + k0 + lc + 4];
                af[3] = sA[(m0 + 8) * APACT + kk + k0 + lc + 4];
#pragma unroll
                for (int nt = 0; nt < 4; nt++) mma_tf32(d[mt][nt], af, bf[nt]);
            }
        }
        __syncthreads();
    }
    // epilogue3: bias + red.add scatter to g_agg[col]
#pragma unroll
    for (int mt = 0; mt < 4; mt++)
#pragma unroll
        for (int nt = 0; nt < 4; nt++) {
            int e0 = wm + mt * 16 + lr;
            int col = wn + nt * 8 + 2 * lc;
            float2 bv = *(const float2*)&be3[col];
            int t0 = s_col[e0], t1 = s_col[e0 + 8];
            red_add_f2(&g_agg[t0 * H + col], d[mt][nt][0] + bv.x, d[mt][nt][1] + bv.y);
            red_add_f2(&g_agg[t1 * H + col], d[mt][nt][2] + bv.x, d[mt][nt][3] + bv.y);
        }
}

// ---------------------------------------------------------------- node MLP + residual + LN (fp32)
__global__ __launch_bounds__(256, 2)
void node_kernel(const float* __restrict__ Wn1, const float* __restrict__ bn1,
                 const float* __restrict__ Wn2, const float* __restrict__ bn2,
                 const float* __restrict__ Wn3, const float* __restrict__ bn3,
                 const float* __restrict__ lng, const float* __restrict__ lnb,
                 float* __restrict__ out) {
    extern __shared__ float smem[];
    float* As = smem;
    float* Bs = As + BM * BK;
    float* acts = Bs + BK * H;

    int tid = threadIdx.x;
    int nb = blockIdx.x * BM;
    int tx = tid & 15, ty = tid >> 4;
    int le = tid >> 1;
    int lk = (tid & 1) * 4;
    int wk = tid >> 5;
    int wn = (tid & 31) * 4;

    float c[8][8];
#pragma unroll
    for (int i = 0; i < 8; i++)
#pragma unroll
        for (int j = 0; j < 8; j++) c[i][j] = 0.f;

    for (int kk = 0; kk < KN; kk += BK) {
        int node = nb + le;
        float4 av = make_float4(0.f, 0.f, 0.f, 0.f);
        if (node < N_NODES) {
            if (kk < 128) av = *(const float4*)&g_h[node * H + kk + lk];
            else          av = *(const float4*)&g_agg[node * H + (kk - 128) + lk];
        }
        *(float4*)&As[le * BK + lk] = av;
        *(float4*)&Bs[wk * H + wn] = *(const float4*)&Wn1[(kk + wk) * H + wn];
        __syncthreads();
#pragma unroll
        for (int k = 0; k < BK; k++) {
            float a[8];
#pragma unroll
            for (int i = 0; i < 8; i++) a[i] = As[(ty * 8 + i) * BK + k];
            float4 b0 = *(float4*)&Bs[k * H + tx * 8];
            float4 b1 = *(float4*)&Bs[k * H + tx * 8 + 4];
            float bb[8] = {b0.x, b0.y, b0.z, b0.w, b1.x, b1.y, b1.z, b1.w};
#pragma unroll
            for (int i = 0; i < 8; i++)
#pragma unroll
                for (int j = 0; j < 8; j++) c[i][j] += a[i] * bb[j];
        }
        __syncthreads();
    }
    {
        float4 t0 = *(const float4*)&bn1[tx * 8];
        float4 t1 = *(const float4*)&bn1[tx * 8 + 4];
        float bias[8] = {t0.x, t0.y, t0.z, t0.w, t1.x, t1.y, t1.z, t1.w};
#pragma unroll
        for (int i = 0; i < 8; i++) {
            float4 v0, v1;
            v0.x = fmaxf(c[i][0] + bias[0], 0.f); v0.y = fmaxf(c[i][1] + bias[1], 0.f);
            v0.z = fmaxf(c[i][2] + bias[2], 0.f); v0.w = fmaxf(c[i][3] + bias[3], 0.f);
            v1.x = fmaxf(c[i][4] + bias[4], 0.f); v1.y = fmaxf(c[i][5] + bias[5], 0.f);
            v1.z = fmaxf(c[i][6] + bias[6], 0.f); v1.w = fmaxf(c[i][7] + bias[7], 0.f);
            *(float4*)&acts[(ty * 8 + i) * AP + tx * 8] = v0;
            *(float4*)&acts[(ty * 8 + i) * AP + tx * 8 + 4] = v1;
        }
    }
    __syncthreads();

#pragma unroll
    for (int i = 0; i < 8; i++)
#pragma unroll
        for (int j = 0; j < 8; j++) c[i][j] = 0.f;
    for (int kk = 0; kk < H; kk += BK) {
        *(float4*)&Bs[wk * H + wn] = *(const float4*)&Wn2[(kk + wk) * H + wn];
        __syncthreads();
#pragma unroll
        for (int k = 0; k < BK; k++) {
            float a[8];
#pragma unroll
            for (int i = 0; i < 8; i++) a[i] = acts[(ty * 8 + i) * AP + kk + k];
            float4 b0 = *(float4*)&Bs[k * H + tx * 8];
            float4 b1 = *(float4*)&Bs[k * H + tx * 8 + 4];
            float bb[8] = {b0.x, b0.y, b0.z, b0.w, b1.x, b1.y, b1.z, b1.w};
#pragma unroll
            for (int i = 0; i < 8; i++)
#pragma unroll
                for (int j = 0; j < 8; j++) c[i][j] += a[i] * bb[j];
        }
        __syncthreads();
    }
    {
        float4 t0 = *(const float4*)&bn2[tx * 8];
        float4 t1 = *(const float4*)&bn2[tx * 8 + 4];
        float bias[8] = {t0.x, t0.y, t0.z, t0.w, t1.x, t1.y, t1.z, t1.w};
        float m2[8][8];
#pragma unroll
        for (int i = 0; i < 8; i++)
#pragma unroll
            for (int j = 0; j < 8; j++) m2[i][j] = fmaxf(c[i][j] + bias[j], 0.f);
        __syncthreads();
#pragma unroll
        for (int i = 0; i < 8; i++) {
            *(float4*)&acts[(ty * 8 + i) * AP + tx * 8]     = make_float4(m2[i][0], m2[i][1], m2[i][2], m2[i][3]);
            *(float4*)&acts[(ty * 8 + i) * AP + tx * 8 + 4] = make_float4(m2[i][4], m2[i][5], m2[i][6], m2[i][7]);
        }
    }
    __syncthreads();

#pragma unroll
    for (int i = 0; i < 8; i++)
#pragma unroll
        for (int j = 0; j < 8; j++) c[i][j] = 0.f;
    for (int kk = 0; kk < H; kk += BK) {
        *(float4*)&Bs[wk * H + wn] = *(const float4*)&Wn3[(kk + wk) * H + wn];
        __syncthreads();
#pragma unroll
        for (int k = 0; k < BK; k++) {
            float a[8];
#pragma unroll
            for (int i = 0; i < 8; i++) a[i] = acts[(ty * 8 + i) * AP + kk + k];
            float4 b0 = *(float4*)&Bs[k * H + tx * 8];
            float4 b1 = *(float4*)&Bs[k * H + tx * 8 + 4];
            float bb[8] = {b0.x, b0.y, b0.z, b0.w, b1.x, b1.y, b1.z, b1.w};
#pragma unroll
            for (int i = 0; i < 8; i++)
#pragma unroll
                for (int j = 0; j < 8; j++) c[i][j] += a[i] * bb[j];
        }
        __syncthreads();
    }
    {
        float4 t0 = *(const float4*)&bn3[tx * 8];
        float4 t1 = *(const float4*)&bn3[tx * 8 + 4];
        float bias[8] = {t0.x, t0.y, t0.z, t0.w, t1.x, t1.y, t1.z, t1.w};
#pragma unroll
        for (int i = 0; i < 8; i++) {
            int node = nb + ty * 8 + i;
            float4 h0 = make_float4(0.f, 0.f, 0.f, 0.f), h1 = make_float4(0.f, 0.f, 0.f, 0.f);
            if (node < N_NODES) {
                h0 = *(const float4*)&g_h[node * H + tx * 8];
                h1 = *(const float4*)&g_h[node * H + tx * 8 + 4];
            }
            *(float4*)&acts[(ty * 8 + i) * AP + tx * 8] =
                make_float4(h0.x + c[i][0] + bias[0], h0.y + c[i][1] + bias[1],
                            h0.z + c[i][2] + bias[2], h0.w + c[i][3] + bias[3]);
            *(float4*)&acts[(ty * 8 + i) * AP + tx * 8 + 4] =
                make_float4(h1.x + c[i][4] + bias[4], h1.y + c[i][5] + bias[5],
                            h1.z + c[i][6] + bias[6], h1.w + c[i][7] + bias[7]);
        }
    }
    __syncthreads();

    {
        int lane = tid & 31, warp = tid >> 5;
        for (int r = warp * 16; r < warp * 16 + 16; r++) {
            int node = nb + r;
            float v0 = acts[r * AP + lane];
            float v1 = acts[r * AP + lane + 32];
            float v2 = acts[r * AP + lane + 64];
            float v3 = acts[r * AP + lane + 96];
            float s = v0 + v1 + v2 + v3;
            float q = v0 * v0 + v1 * v1 + v2 * v2 + v3 * v3;
#pragma unroll
            for (int off = 16; off > 0; off >>= 1) {
                s += __shfl_xor_sync(0xffffffffu, s, off);
                q += __shfl_xor_sync(0xffffffffu, q, off);
            }
            float mean = s * (1.f / 128.f);
            float var = q * (1.f / 128.f) - mean * mean;
            float rstd = rsqrtf(var + 1e-5f);
            if (node < N_NODES) {
                out[node * H + lane]      = (v0 - mean) * rstd * lng[lane]      + lnb[lane];
                out[node * H + lane + 32] = (v1 - mean) * rstd * lng[lane + 32] + lnb[lane + 32];
                out[node * H + lane + 64] = (v2 - mean) * rstd * lng[lane + 64] + lnb[lane + 64];
                out[node * H + lane + 96] = (v3 - mean) * rstd * lng[lane + 96] + lnb[lane + 96];
            }
        }
    }
}

// ----------------------------------------------------------------
extern "C" void kernel_launch(void* const* d_in, const int* in_sizes, int n_in,
                              void* d_out, int out_size) {
    const float* x    = (const float*)d_in[0];
    const float* pos  = (const float*)d_in[1];
    const int*   ei   = (const int*)d_in[2];
    const float* W_in = (const float*)d_in[3];
    const float* b_in = (const float*)d_in[4];
    const float* We1  = (const float*)d_in[5];
    const float* be1  = (const float*)d_in[6];
    const float* We2  = (const float*)d_in[7];
    const float* be2  = (const float*)d_in[8];
    const float* We3  = (const float*)d_in[9];
    const float* be3  = (const float*)d_in[10];
    const float* Wn1  = (const float*)d_in[11];
    const float* bn1  = (const float*)d_in[12];
    const float* Wn2  = (const float*)d_in[13];
    const float* bn2  = (const float*)d_in[14];
    const float* Wn3  = (const float*)d_in[15];
    const float* bn3  = (const float*)d_in[16];
    const float* ln_g = (const float*)d_in[17];
    const float* ln_b = (const float*)d_in[18];

    const int* rowIdx = ei;
    const int* colIdx = ei + N_EDGES;

    size_t smem_edge = (size_t)(256 + 128 * APACT + 32 * BPAD) * 4;
    size_t smem_node = (size_t)(BM * BK + BK * H + BM * AP) * sizeof(float);
    cudaFuncSetAttribute(edge_kernel, cudaFuncAttributeMaxDynamicSharedMemorySize, (int)smem_edge);
    cudaFuncSetAttribute(node_kernel, cudaFuncAttributeMaxDynamicSharedMemorySize, (int)smem_node);

    float* hptr = nullptr;
    cudaGetSymbolAddress((void**)&hptr, g_h);

    embed_kernel<<<(N_NODES * H + 255) / 256, 256>>>(x, W_in, b_in);
    ea_kernel<<<(N_EDGES + 255) / 256, 256>>>(pos, rowIdx, colIdx);

    int edge_blocks = N_EDGES / BM;
    int node_blocks = (N_NODES + BM - 1) / BM;
    int zero_blocks = (N_NODES * H / 4) / 256;

    for (int l = 0; l < LAYERS; l++) {
        zero_agg_kernel<<<zero_blocks, 256>>>();
        edge_kernel<<<edge_blocks, 256, smem_edge>>>(
            We1 + (size_t)l * KE * H, be1 + l * H,
            We2 + (size_t)l * H * H,  be2 + l * H,
            We3 + (size_t)l * H * H,  be3 + l * H,
            rowIdx, colIdx);
        float* outp = (l == LAYERS - 1) ? (float*)d_out : hptr;
        node_kernel<<<node_blocks, 256, smem_node>>>(
            Wn1 + (size_t)l * KN * H, bn1 + l * H,
            Wn2 + (size_t)l * H * H,  bn2 + l * H,
            Wn3 + (size_t)l * H * H,  bn3 + l * H,
            ln_g + l * H, ln_b + l * H, outp);
    }
}

// round 3
// speedup vs baseline: 3.2398x; 1.4607x over previous
#include <cuda_runtime.h>
#include <cuda_bf16.h>
#include <math.h>

#define N_NODES 50000
#define N_EDGES 800000
#define H 128
#define LAYERS 4
#define KE 263
#define KN 256
#define BM 128
#define BK 8
#define AP 132

#define CH_PITCH 40     // A chunk pitch (bf16 words): 80B -> conflict-free ldmatrix
#define ACT_PITCH 136   // acts / B pitch (bf16 words): 272B -> conflict-free ldmatrix
// smem offsets (bytes): idx 1024 | sA 34816 | sB 34816
#define SM_A_OFF 1024
#define SM_B_OFF (1024 + 34816)
#define SM_TOTAL (1024 + 34816 + 34816)

__device__ float g_h[N_NODES * H];
__device__ float g_agg[N_NODES * H];
__device__ float g_ea[N_EDGES * 4];

__device__ __forceinline__ void red_add_f2(float* p, float a, float b) {
    asm volatile("red.global.add.v2.f32 [%0], {%1,%2};"
                 :: "l"(p), "f"(a), "f"(b) : "memory");
}

__device__ __forceinline__ unsigned pack_bf2(float lo, float hi) {
    __nv_bfloat162 v = __floats2bfloat162_rn(lo, hi);
    return *(unsigned*)&v;
}

__device__ __forceinline__ void ldsm_x4(unsigned& r0, unsigned& r1, unsigned& r2, unsigned& r3,
                                        unsigned addr) {
    asm volatile("ldmatrix.sync.aligned.m8n8.x4.shared.b16 {%0,%1,%2,%3}, [%4];"
                 : "=r"(r0), "=r"(r1), "=r"(r2), "=r"(r3) : "r"(addr));
}

__device__ __forceinline__ void ldsm_x4t(unsigned& r0, unsigned& r1, unsigned& r2, unsigned& r3,
                                         unsigned addr) {
    asm volatile("ldmatrix.sync.aligned.m8n8.x4.trans.shared.b16 {%0,%1,%2,%3}, [%4];"
                 : "=r"(r0), "=r"(r1), "=r"(r2), "=r"(r3) : "r"(addr));
}

__device__ __forceinline__ void mma_bf16(float d[4], const unsigned a[4], const unsigned b[2]) {
    asm volatile("mma.sync.aligned.m16n8k16.row.col.f32.bf16.bf16.f32 "
                 "{%0,%1,%2,%3}, {%4,%5,%6,%7}, {%8,%9}, {%0,%1,%2,%3};"
                 : "+f"(d[0]), "+f"(d[1]), "+f"(d[2]), "+f"(d[3])
                 : "r"(a[0]), "r"(a[1]), "r"(a[2]), "r"(a[3]), "r"(b[0]), "r"(b[1]));
}

// ---------------------------------------------------------------- embed
__global__ void embed_kernel(const float* __restrict__ x,
                             const float* __restrict__ W,
                             const float* __restrict__ b) {
    int gid = blockIdx.x * blockDim.x + threadIdx.x;
    if (gid >= N_NODES * H) return;
    int i = gid >> 7;
    int j = gid & (H - 1);
    const float* xr = x + i * 16;
    float acc = b[j];
#pragma unroll
    for (int k = 0; k < 16; k++) acc += xr[k] * W[k * H + j];
    g_h[gid] = acc;
}

// ---------------------------------------------------------------- edge_attr
__global__ void ea_kernel(const float* __restrict__ pos,
                          const int* __restrict__ rowIdx,
                          const int* __restrict__ colIdx) {
    int e = blockIdx.x * blockDim.x + threadIdx.x;
    if (e >= N_EDGES) return;
    int r = rowIdx[e], c = colIdx[e];
    float dx = pos[c * 3 + 0] - pos[r * 3 + 0];
    float dy = pos[c * 3 + 1] - pos[r * 3 + 1];
    float dz = pos[c * 3 + 2] - pos[r * 3 + 2];
    float d = sqrtf(dx * dx + dy * dy + dz * dz);
    *(float4*)&g_ea[e * 4] = make_float4(dx, dy, dz, d);
}

__global__ void zero_agg_kernel() {
    int gid = blockIdx.x * blockDim.x + threadIdx.x;
    ((float4*)g_agg)[gid] = make_float4(0.f, 0.f, 0.f, 0.f);
}

// ---------------------------------------------------------------- fused edge MLP: bf16 mma + ldmatrix
__global__ __launch_bounds__(256, 2)
void edge_kernel(const float* __restrict__ We1, const float* __restrict__ be1,
                 const float* __restrict__ We2, const float* __restrict__ be2,
                 const float* __restrict__ We3, const float* __restrict__ be3,
                 const int* __restrict__ rowIdx, const int* __restrict__ colIdx) {
    extern __shared__ __align__(16) unsigned smem_u[];
    int* s_col = (int*)smem_u;
    int* s_row = s_col + 128;
    unsigned* sA = smem_u + SM_A_OFF / 4;   // bf16 tile region (u32 view)
    unsigned* sB = smem_u + SM_B_OFF / 4;

    unsigned sbase;
    asm("{ .reg .u64 t; cvta.to.shared.u64 t, %1; cvt.u32.u64 %0, t; }"
        : "=r"(sbase) : "l"(smem_u));
    unsigned sAb = sbase + SM_A_OFF;
    unsigned sBb = sbase + SM_B_OFF;

    int tid = threadIdx.x;
    int eb = blockIdx.x * BM;

    if (tid < 128) s_col[tid] = colIdx[eb + tid];
    else           s_row[tid - 128] = rowIdx[eb + tid - 128];
    __syncthreads();

    int warp = tid >> 5, lane = tid & 31;
    int lr = lane >> 2, lc = lane & 3;
    int wm = (warp & 1) * 64;
    int wn = (warp >> 1) * 32;

    int r = tid >> 1, half = tid & 1;           // A staging
    int br = tid >> 3, bs = (tid & 7) * 16;     // B staging

    float d[4][4][4];
#pragma unroll
    for (int mt = 0; mt < 4; mt++)
#pragma unroll
        for (int nt = 0; nt < 4; nt++)
#pragma unroll
            for (int i = 0; i < 4; i++) d[mt][nt][i] = 0.f;

    // ================= GEMM1: [h[col] | h[row] | ea7] @ We1  (K = 272 padded)
    for (int ch = 0; ch < 9; ch++) {
        int kk = ch * 32;
        // ---- stage A chunk as bf16, pitch CH_PITCH
        if (ch < 8) {
            int node = (ch < 4) ? s_col[r] : s_row[r];
            int kbase = (ch < 4) ? kk : (kk - 128);
            const float4* p = (const float4*)&g_h[node * H + kbase + half * 16];
            unsigned* dst = &sA[(r * CH_PITCH + half * 16) >> 1];
#pragma unroll
            for (int j = 0; j < 4; j++) {
                float4 v = p[j];
                dst[2 * j]     = pack_bf2(v.x, v.y);
                dst[2 * j + 1] = pack_bf2(v.z, v.w);
            }
        } else if (half == 0) {
            float4 ea = *(const float4*)&g_ea[(eb + r) * 4];
            int ci = s_col[r] * H, ri = s_row[r] * H;
            float rm0 = g_h[ci + 3] - g_h[ri + 3];
            float rm1 = g_h[ci + 4] - g_h[ri + 4];
            float rm2 = g_h[ci + 5] - g_h[ri + 5];
            unsigned* dst = &sA[(r * CH_PITCH) >> 1];
            dst[0] = pack_bf2(ea.x, ea.y);
            dst[1] = pack_bf2(ea.z, ea.w);
            dst[2] = pack_bf2(rm0, rm1);
            dst[3] = pack_bf2(rm2, 0.f);
            dst[4] = 0u; dst[5] = 0u; dst[6] = 0u; dst[7] = 0u;
        }
        // ---- stage B chunk (32 x 128) as bf16, pitch ACT_PITCH
        {
            int row_g = kk + br;
            bool ok = row_g < KE;
            const float4* wp = (const float4*)&We1[(size_t)row_g * H + bs];
            unsigned* dst = &sB[(br * ACT_PITCH + bs) >> 1];
#pragma unroll
            for (int j = 0; j < 4; j++) {
                float4 v = ok ? wp[j] : make_float4(0.f, 0.f, 0.f, 0.f);
                dst[2 * j]     = pack_bf2(v.x, v.y);
                dst[2 * j + 1] = pack_bf2(v.z, v.w);
            }
        }
        __syncthreads();
        int nk16 = (ch < 8) ? 2 : 1;
        for (int k16 = 0; k16 < nk16; k16++) {
            int k0 = k16 * 16;
            unsigned a[4][4], b[4][2];
#pragma unroll
            for (int mt = 0; mt < 4; mt++) {
                unsigned addr = sAb + ((wm + mt * 16 + (lane & 15)) * CH_PITCH
                                       + k0 + ((lane >> 4) << 3)) * 2;
                ldsm_x4(a[mt][0], a[mt][1], a[mt][2], a[mt][3], addr);
            }
#pragma unroll
            for (int np = 0; np < 2; np++) {
                unsigned addr = sBb + ((k0 + (lane & 7) + (lane & 8)) * ACT_PITCH
                                       + wn + np * 16 + ((lane >> 4) << 3)) * 2;
                ldsm_x4t(b[2 * np][0], b[2 * np][1], b[2 * np + 1][0], b[2 * np + 1][1], addr);
            }
#pragma unroll
            for (int mt = 0; mt < 4; mt++)
#pragma unroll
                for (int nt = 0; nt < 4; nt++) mma_bf16(d[mt][nt], a[mt], b[nt]);
        }
        __syncthreads();
    }
    // epilogue1: bias + relu -> acts (bf16, pitch ACT_PITCH) in sA region
#pragma unroll
    for (int mt = 0; mt < 4; mt++)
#pragma unroll
        for (int nt = 0; nt < 4; nt++) {
            int row = wm + mt * 16 + lr;
            int col = wn + nt * 8 + 2 * lc;
            float2 bv = *(const float2*)&be1[col];
            sA[(row * ACT_PITCH + col) >> 1] =
                pack_bf2(fmaxf(d[mt][nt][0] + bv.x, 0.f), fmaxf(d[mt][nt][1] + bv.y, 0.f));
            sA[((row + 8) * ACT_PITCH + col) >> 1] =
                pack_bf2(fmaxf(d[mt][nt][2] + bv.x, 0.f), fmaxf(d[mt][nt][3] + bv.y, 0.f));
        }
    __syncthreads();

    // ================= GEMM2: relu(acts @ We2 + be2), K = 128, full B resident
#pragma unroll
    for (int mt = 0; mt < 4; mt++)
#pragma unroll
        for (int nt = 0; nt < 4; nt++)
#pragma unroll
            for (int i = 0; i < 4; i++) d[mt][nt][i] = 0.f;
#pragma unroll
    for (int j4 = 0; j4 < 4; j4++) {
        int row_g = j4 * 32 + br;
        const float4* wp = (const float4*)&We2[(size_t)row_g * H + bs];
        unsigned* dst = &sB[(row_g * ACT_PITCH + bs) >> 1];
#pragma unroll
        for (int j = 0; j < 4; j++) {
            float4 v = wp[j];
            dst[2 * j]     = pack_bf2(v.x, v.y);
            dst[2 * j + 1] = pack_bf2(v.z, v.w);
        }
    }
    __syncthreads();
#pragma unroll
    for (int k16 = 0; k16 < 8; k16++) {
        int k0 = k16 * 16;
        unsigned a[4][4], b[4][2];
#pragma unroll
        for (int mt = 0; mt < 4; mt++) {
            unsigned addr = sAb + ((wm + mt * 16 + (lane & 15)) * ACT_PITCH
                                   + k0 + ((lane >> 4) << 3)) * 2;
            ldsm_x4(a[mt][0], a[mt][1], a[mt][2], a[mt][3], addr);
        }
#pragma unroll
        for (int np = 0; np < 2; np++) {
            unsigned addr = sBb + ((k0 + (lane & 7) + (lane & 8)) * ACT_PITCH
                                   + wn + np * 16 + ((lane >> 4) << 3)) * 2;
            ldsm_x4t(b[2 * np][0], b[2 * np][1], b[2 * np + 1][0], b[2 * np + 1][1], addr);
        }
#pragma unroll
        for (int mt = 0; mt < 4; mt++)
#pragma unroll
            for (int nt = 0; nt < 4; nt++) mma_bf16(d[mt][nt], a[mt], b[nt]);
    }
    __syncthreads();
    // epilogue2: bias + relu -> acts (in place, after barrier)
#pragma unroll
    for (int mt = 0; mt < 4; mt++)
#pragma unroll
        for (int nt = 0; nt < 4; nt++) {
            int row = wm + mt * 16 + lr;
            int col = wn + nt * 8 + 2 * lc;
            float2 bv = *(const float2*)&be2[col];
            sA[(row * ACT_PITCH + col) >> 1] =
                pack_bf2(fmaxf(d[mt][nt][0] + bv.x, 0.f), fmaxf(d[mt][nt][1] + bv.y, 0.f));
            sA[((row + 8) * ACT_PITCH + col) >> 1] =
                pack_bf2(fmaxf(d[mt][nt][2] + bv.x, 0.f), fmaxf(d[mt][nt][3] + bv.y, 0.f));
        }
    __syncthreads();

    // ================= GEMM3: acts @ We3 + be3 -> scatter red.add
#pragma unroll
    for (int mt = 0; mt < 4; mt++)
#pragma unroll
        for (int nt = 0; nt < 4; nt++)
#pragma unroll
            for (int i = 0; i < 4; i++) d[mt][nt][i] = 0.f;
#pragma unroll
    for (int j4 = 0; j4 < 4; j4++) {
        int row_g = j4 * 32 + br;
        const float4* wp = (const float4*)&We3[(size_t)row_g * H + bs];
        unsigned* dst = &sB[(row_g * ACT_PITCH + bs) >> 1];
#pragma unroll
        for (int j = 0; j < 4; j++) {
            float4 v = wp[j];
            dst[2 * j]     = pack_bf2(v.x, v.y);
            dst[2 * j + 1] = pack_bf2(v.z, v.w);
        }
    }
    __syncthreads();
#pragma unroll
    for (int k16 = 0; k16 < 8; k16++) {
        int k0 = k16 * 16;
        unsigned a[4][4], b[4][2];
#pragma unroll
        for (int mt = 0; mt < 4; mt++) {
            unsigned addr = sAb + ((wm + mt * 16 + (lane & 15)) * ACT_PITCH
                                   + k0 + ((lane >> 4) << 3)) * 2;
            ldsm_x4(a[mt][0], a[mt][1], a[mt][2], a[mt][3], addr);
        }
#pragma unroll
        for (int np = 0; np < 2; np++) {
            unsigned addr = sBb + ((k0 + (lane & 7) + (lane & 8)) * ACT_PITCH
                                   + wn + np * 16 + ((lane >> 4) << 3)) * 2;
            ldsm_x4t(b[2 * np][0], b[2 * np][1], b[2 * np + 1][0], b[2 * np + 1][1], addr);
        }
#pragma unroll
        for (int mt = 0; mt < 4; mt++)
#pragma unroll
            for (int nt = 0; nt < 4; nt++) mma_bf16(d[mt][nt], a[mt], b[nt]);
    }
    // epilogue3: bias + scatter
#pragma unroll
    for (int mt = 0; mt < 4; mt++)
#pragma unroll
        for (int nt = 0; nt < 4; nt++) {
            int e0 = wm + mt * 16 + lr;
            int col = wn + nt * 8 + 2 * lc;
            float2 bv = *(const float2*)&be3[col];
            int t0 = s_col[e0], t1 = s_col[e0 + 8];
            red_add_f2(&g_agg[t0 * H + col], d[mt][nt][0] + bv.x, d[mt][nt][1] + bv.y);
            red_add_f2(&g_agg[t1 * H + col], d[mt][nt][2] + bv.x, d[mt][nt][3] + bv.y);
        }
}

// ---------------------------------------------------------------- node MLP + residual + LN (fp32)
__global__ __launch_bounds__(256, 2)
void node_kernel(const float* __restrict__ Wn1, const float* __restrict__ bn1,
                 const float* __restrict__ Wn2, const float* __restrict__ bn2,
                 const float* __restrict__ Wn3, const float* __restrict__ bn3,
                 const float* __restrict__ lng, const float* __restrict__ lnb,
                 float* __restrict__ out) {
    extern __shared__ float smem[];
    float* As = smem;
    float* Bs = As + BM * BK;
    float* acts = Bs + BK * H;

    int tid = threadIdx.x;
    int nb = blockIdx.x * BM;
    int tx = tid & 15, ty = tid >> 4;
    int le = tid >> 1;
    int lk = (tid & 1) * 4;
    int wk = tid >> 5;
    int wn = (tid & 31) * 4;

    float c[8][8];
#pragma unroll
    for (int i = 0; i < 8; i++)
#pragma unroll
        for (int j = 0; j < 8; j++) c[i][j] = 0.f;

    for (int kk = 0; kk < KN; kk += BK) {
        int node = nb + le;
        float4 av = make_float4(0.f, 0.f, 0.f, 0.f);
        if (node < N_NODES) {
            if (kk < 128) av = *(const float4*)&g_h[node * H + kk + lk];
            else          av = *(const float4*)&g_agg[node * H + (kk - 128) + lk];
        }
        *(float4*)&As[le * BK + lk] = av;
        *(float4*)&Bs[wk * H + wn] = *(const float4*)&Wn1[(kk + wk) * H + wn];
        __syncthreads();
#pragma unroll
        for (int k = 0; k < BK; k++) {
            float a[8];
#pragma unroll
            for (int i = 0; i < 8; i++) a[i] = As[(ty * 8 + i) * BK + k];
            float4 b0 = *(float4*)&Bs[k * H + tx * 8];
            float4 b1 = *(float4*)&Bs[k * H + tx * 8 + 4];
            float bb[8] = {b0.x, b0.y, b0.z, b0.w, b1.x, b1.y, b1.z, b1.w};
#pragma unroll
            for (int i = 0; i < 8; i++)
#pragma unroll
                for (int j = 0; j < 8; j++) c[i][j] += a[i] * bb[j];
        }
        __syncthreads();
    }
    {
        float4 t0 = *(const float4*)&bn1[tx * 8];
        float4 t1 = *(const float4*)&bn1[tx * 8 + 4];
        float bias[8] = {t0.x, t0.y, t0.z, t0.w, t1.x, t1.y, t1.z, t1.w};
#pragma unroll
        for (int i = 0; i < 8; i++) {
            float4 v0, v1;
            v0.x = fmaxf(c[i][0] + bias[0], 0.f); v0.y = fmaxf(c[i][1] + bias[1], 0.f);
            v0.z = fmaxf(c[i][2] + bias[2], 0.f); v0.w = fmaxf(c[i][3] + bias[3], 0.f);
            v1.x = fmaxf(c[i][4] + bias[4], 0.f); v1.y = fmaxf(c[i][5] + bias[5], 0.f);
            v1.z = fmaxf(c[i][6] + bias[6], 0.f); v1.w = fmaxf(c[i][7] + bias[7], 0.f);
            *(float4*)&acts[(ty * 8 + i) * AP + tx * 8] = v0;
            *(float4*)&acts[(ty * 8 + i) * AP + tx * 8 + 4] = v1;
        }
    }
    __syncthreads();

#pragma unroll
    for (int i = 0; i < 8; i++)
#pragma unroll
        for (int j = 0; j < 8; j++) c[i][j] = 0.f;
    for (int kk = 0; kk < H; kk += BK) {
        *(float4*)&Bs[wk * H + wn] = *(const float4*)&Wn2[(kk + wk) * H + wn];
        __syncthreads();
#pragma unroll
        for (int k = 0; k < BK; k++) {
            float a[8];
#pragma unroll
            for (int i = 0; i < 8; i++) a[i] = acts[(ty * 8 + i) * AP + kk + k];
            float4 b0 = *(float4*)&Bs[k * H + tx * 8];
            float4 b1 = *(float4*)&Bs[k * H + tx * 8 + 4];
            float bb[8] = {b0.x, b0.y, b0.z, b0.w, b1.x, b1.y, b1.z, b1.w};
#pragma unroll
            for (int i = 0; i < 8; i++)
#pragma unroll
                for (int j = 0; j < 8; j++) c[i][j] += a[i] * bb[j];
        }
        __syncthreads();
    }
    {
        float4 t0 = *(const float4*)&bn2[tx * 8];
        float4 t1 = *(const float4*)&bn2[tx * 8 + 4];
        float bias[8] = {t0.x, t0.y, t0.z, t0.w, t1.x, t1.y, t1.z, t1.w};
        float m2[8][8];
#pragma unroll
        for (int i = 0; i < 8; i++)
#pragma unroll
            for (int j = 0; j < 8; j++) m2[i][j] = fmaxf(c[i][j] + bias[j], 0.f);
        __syncthreads();
#pragma unroll
        for (int i = 0; i < 8; i++) {
            *(float4*)&acts[(ty * 8 + i) * AP + tx * 8]     = make_float4(m2[i][0], m2[i][1], m2[i][2], m2[i][3]);
            *(float4*)&acts[(ty * 8 + i) * AP + tx * 8 + 4] = make_float4(m2[i][4], m2[i][5], m2[i][6], m2[i][7]);
        }
    }
    __syncthreads();

#pragma unroll
    for (int i = 0; i < 8; i++)
#pragma unroll
        for (int j = 0; j < 8; j++) c[i][j] = 0.f;
    for (int kk = 0; kk < H; kk += BK) {
        *(float4*)&Bs[wk * H + wn] = *(const float4*)&Wn3[(kk + wk) * H + wn];
        __syncthreads();
#pragma unroll
        for (int k = 0; k < BK; k++) {
            float a[8];
#pragma unroll
            for (int i = 0; i < 8; i++) a[i] = acts[(ty * 8 + i) * AP + kk + k];
            float4 b0 = *(float4*)&Bs[k * H + tx * 8];
            float4 b1 = *(float4*)&Bs[k * H + tx * 8 + 4];
            float bb[8] = {b0.x, b0.y, b0.z, b0.w, b1.x, b1.y, b1.z, b1.w};
#pragma unroll
            for (int i = 0; i < 8; i++)
#pragma unroll
                for (int j = 0; j < 8; j++) c[i][j] += a[i] * bb[j];
        }
        __syncthreads();
    }
    {
        float4 t0 = *(const float4*)&bn3[tx * 8];
        float4 t1 = *(const float4*)&bn3[tx * 8 + 4];
        float bias[8] = {t0.x, t0.y, t0.z, t0.w, t1.x, t1.y, t1.z, t1.w};
#pragma unroll
        for (int i = 0; i < 8; i++) {
            int node = nb + ty * 8 + i;
            float4 h0 = make_float4(0.f, 0.f, 0.f, 0.f), h1 = make_float4(0.f, 0.f, 0.f, 0.f);
            if (node < N_NODES) {
                h0 = *(const float4*)&g_h[node * H + tx * 8];
                h1 = *(const float4*)&g_h[node * H + tx * 8 + 4];
            }
            *(float4*)&acts[(ty * 8 + i) * AP + tx * 8] =
                make_float4(h0.x + c[i][0] + bias[0], h0.y + c[i][1] + bias[1],
                            h0.z + c[i][2] + bias[2], h0.w + c[i][3] + bias[3]);
            *(float4*)&acts[(ty * 8 + i) * AP + tx * 8 + 4] =
                make_float4(h1.x + c[i][4] + bias[4], h1.y + c[i][5] + bias[5],
                            h1.z + c[i][6] + bias[6], h1.w + c[i][7] + bias[7]);
        }
    }
    __syncthreads();

    {
        int lane = tid & 31, warp = tid >> 5;
        for (int r = warp * 16; r < warp * 16 + 16; r++) {
            int node = nb + r;
            float v0 = acts[r * AP + lane];
            float v1 = acts[r * AP + lane + 32];
            float v2 = acts[r * AP + lane + 64];
            float v3 = acts[r * AP + lane + 96];
            float s = v0 + v1 + v2 + v3;
            float q = v0 * v0 + v1 * v1 + v2 * v2 + v3 * v3;
#pragma unroll
            for (int off = 16; off > 0; off >>= 1) {
                s += __shfl_xor_sync(0xffffffffu, s, off);
                q += __shfl_xor_sync(0xffffffffu, q, off);
            }
            float mean = s * (1.f / 128.f);
            float var = q * (1.f / 128.f) - mean * mean;
            float rstd = rsqrtf(var + 1e-5f);
            if (node < N_NODES) {
                out[node * H + lane]      = (v0 - mean) * rstd * lng[lane]      + lnb[lane];
                out[node * H + lane + 32] = (v1 - mean) * rstd * lng[lane + 32] + lnb[lane + 32];
                out[node * H + lane + 64] = (v2 - mean) * rstd * lng[lane + 64] + lnb[lane + 64];
                out[node * H + lane + 96] = (v3 - mean) * rstd * lng[lane + 96] + lnb[lane + 96];
            }
        }
    }
}

// ----------------------------------------------------------------
extern "C" void kernel_launch(void* const* d_in, const int* in_sizes, int n_in,
                              void* d_out, int out_size) {
    const float* x    = (const float*)d_in[0];
    const float* pos  = (const float*)d_in[1];
    const int*   ei   = (const int*)d_in[2];
    const float* W_in = (const float*)d_in[3];
    const float* b_in = (const float*)d_in[4];
    const float* We1  = (const float*)d_in[5];
    const float* be1  = (const float*)d_in[6];
    const float* We2  = (const float*)d_in[7];
    const float* be2  = (const float*)d_in[8];
    const float* We3  = (const float*)d_in[9];
    const float* be3  = (const float*)d_in[10];
    const float* Wn1  = (const float*)d_in[11];
    const float* bn1  = (const float*)d_in[12];
    const float* Wn2  = (const float*)d_in[13];
    const float* bn2  = (const float*)d_in[14];
    const float* Wn3  = (const float*)d_in[15];
    const float* bn3  = (const float*)d_in[16];
    const float* ln_g = (const float*)d_in[17];
    const float* ln_b = (const float*)d_in[18];

    const int* rowIdx = ei;
    const int* colIdx = ei + N_EDGES;

    size_t smem_edge = SM_TOTAL;
    size_t smem_node = (size_t)(BM * BK + BK * H + BM * AP) * sizeof(float);
    cudaFuncSetAttribute(edge_kernel, cudaFuncAttributeMaxDynamicSharedMemorySize, (int)smem_edge);
    cudaFuncSetAttribute(node_kernel, cudaFuncAttributeMaxDynamicSharedMemorySize, (int)smem_node);

    float* hptr = nullptr;
    cudaGetSymbolAddress((void**)&hptr, g_h);

    embed_kernel<<<(N_NODES * H + 255) / 256, 256>>>(x, W_in, b_in);
    ea_kernel<<<(N_EDGES + 255) / 256, 256>>>(pos, rowIdx, colIdx);

    int edge_blocks = N_EDGES / BM;
    int node_blocks = (N_NODES + BM - 1) / BM;
    int zero_blocks = (N_NODES * H / 4) / 256;

    for (int l = 0; l < LAYERS; l++) {
        zero_agg_kernel<<<zero_blocks, 256>>>();
        edge_kernel<<<edge_blocks, 256, smem_edge>>>(
            We1 + (size_t)l * KE * H, be1 + l * H,
            We2 + (size_t)l * H * H,  be2 + l * H,
            We3 + (size_t)l * H * H,  be3 + l * H,
            rowIdx, colIdx);
        float* outp = (l == LAYERS - 1) ? (float*)d_out : hptr;
        node_kernel<<<node_blocks, 256, smem_node>>>(
            Wn1 + (size_t)l * KN * H, bn1 + l * H,
            Wn2 + (size_t)l * H * H,  bn2 + l * H,
            Wn3 + (size_t)l * H * H,  bn3 + l * H,
            ln_g + l * H, ln_b + l * H, outp);
    }
}

// round 4
// speedup vs baseline: 4.6769x; 1.4436x over previous
#include <cuda_runtime.h>
#include <cuda_bf16.h>
#include <math.h>

#define N_NODES 50000
#define N_EDGES 800000
#define H 128
#define LAYERS 4
#define KE 263
#define KN 256
#define BM 128
#define BK 8
#define AP 132
#define KE_PAD 288

// edge smem layout (bytes)
#define IDX_OFF   0
#define ACTS_OFF  1024
#define A8_OFF    35840
#define ABUF0_OFF 41984
#define ABUF1_OFF 52224
#define BBUF0_OFF 62464
#define BBUF1_OFF 71168
#define SMEM_EDGE 79872

__device__ float g_h[N_NODES * H];
__device__ float g_agg[N_NODES * H];
__device__ float g_ea[N_EDGES * 4];
__device__ __nv_bfloat16 g_hb[N_NODES * H];
__device__ __nv_bfloat16 g_We1b[LAYERS * KE_PAD * H];
__device__ __nv_bfloat16 g_We2b[LAYERS * H * H];
__device__ __nv_bfloat16 g_We3b[LAYERS * H * H];

#define CP_COMMIT asm volatile("cp.async.commit_group;" ::: "memory")
#define CP_WAIT1  asm volatile("cp.async.wait_group 1;" ::: "memory")
#define CP_WAIT0  asm volatile("cp.async.wait_group 0;" ::: "memory")

__device__ __forceinline__ void cp16x2(unsigned dst, const void* src) {
    asm volatile("cp.async.cg.shared.global [%0], [%1], 16;\n\t"
                 "cp.async.cg.shared.global [%2], [%3], 16;"
                 :: "r"(dst), "l"(src), "r"(dst + 16), "l"((const char*)src + 16) : "memory");
}

__device__ __forceinline__ void red_add_f2(float* p, float a, float b) {
    asm volatile("red.global.add.v2.f32 [%0], {%1,%2};"
                 :: "l"(p), "f"(a), "f"(b) : "memory");
}

__device__ __forceinline__ unsigned pack_bf2(float lo, float hi) {
    __nv_bfloat162 v = __floats2bfloat162_rn(lo, hi);
    return *(unsigned*)&v;
}

__device__ __forceinline__ void ldsm_x4(unsigned& r0, unsigned& r1, unsigned& r2, unsigned& r3,
                                        unsigned addr) {
    asm volatile("ldmatrix.sync.aligned.m8n8.x4.shared.b16 {%0,%1,%2,%3}, [%4];"
                 : "=r"(r0), "=r"(r1), "=r"(r2), "=r"(r3) : "r"(addr));
}

__device__ __forceinline__ void ldsm_x4t(unsigned& r0, unsigned& r1, unsigned& r2, unsigned& r3,
                                         unsigned addr) {
    asm volatile("ldmatrix.sync.aligned.m8n8.x4.trans.shared.b16 {%0,%1,%2,%3}, [%4];"
                 : "=r"(r0), "=r"(r1), "=r"(r2), "=r"(r3) : "r"(addr));
}

__device__ __forceinline__ void mma_bf16(float d[4], const unsigned a[4], const unsigned b[2]) {
    asm volatile("mma.sync.aligned.m16n8k16.row.col.f32.bf16.bf16.f32 "
                 "{%0,%1,%2,%3}, {%4,%5,%6,%7}, {%8,%9}, {%0,%1,%2,%3};"
                 : "+f"(d[0]), "+f"(d[1]), "+f"(d[2]), "+f"(d[3])
                 : "r"(a[0]), "r"(a[1]), "r"(a[2]), "r"(a[3]), "r"(b[0]), "r"(b[1]));
}

// ---------------------------------------------------------------- weight prep (fp32 -> bf16, pad We1)
__global__ void prep_weights(const float* __restrict__ We1,
                             const float* __restrict__ We2,
                             const float* __restrict__ We3) {
    int id = blockIdx.x * blockDim.x + threadIdx.x;
    const int n1 = LAYERS * KE_PAD * H;
    const int n2 = LAYERS * H * H;
    if (id < n1) {
        int l = id / (KE_PAD * H);
        int rem = id % (KE_PAD * H);
        int r = rem / H, c = rem % H;
        float v = (r < KE) ? We1[((size_t)l * KE + r) * H + c] : 0.f;
        g_We1b[id] = __float2bfloat16(v);
    } else if (id < n1 + n2) {
        int k = id - n1;
        g_We2b[k] = __float2bfloat16(We2[k]);
    } else if (id < n1 + 2 * n2) {
        int k = id - n1 - n2;
        g_We3b[k] = __float2bfloat16(We3[k]);
    }
}

// ---------------------------------------------------------------- embed
__global__ void embed_kernel(const float* __restrict__ x,
                             const float* __restrict__ W,
                             const float* __restrict__ b) {
    int gid = blockIdx.x * blockDim.x + threadIdx.x;
    if (gid >= N_NODES * H) return;
    int i = gid >> 7;
    int j = gid & (H - 1);
    const float* xr = x + i * 16;
    float acc = b[j];
#pragma unroll
    for (int k = 0; k < 16; k++) acc += xr[k] * W[k * H + j];
    g_h[gid] = acc;
    g_hb[gid] = __float2bfloat16(acc);
}

// ---------------------------------------------------------------- edge_attr
__global__ void ea_kernel(const float* __restrict__ pos,
                          const int* __restrict__ rowIdx,
                          const int* __restrict__ colIdx) {
    int e = blockIdx.x * blockDim.x + threadIdx.x;
    if (e >= N_EDGES) return;
    int r = rowIdx[e], c = colIdx[e];
    float dx = pos[c * 3 + 0] - pos[r * 3 + 0];
    float dy = pos[c * 3 + 1] - pos[r * 3 + 1];
    float dz = pos[c * 3 + 2] - pos[r * 3 + 2];
    float d = sqrtf(dx * dx + dy * dy + dz * dz);
    *(float4*)&g_ea[e * 4] = make_float4(dx, dy, dz, d);
}

__global__ void zero_agg_kernel() {
    int gid = blockIdx.x * blockDim.x + threadIdx.x;
    ((float4*)g_agg)[gid] = make_float4(0.f, 0.f, 0.f, 0.f);
}

// ---------------------------------------------------------------- fused edge MLP: cp.async pipelined bf16 mma
__global__ __launch_bounds__(256, 2)
void edge_kernel(int layer,
                 const float* __restrict__ be1, const float* __restrict__ be2,
                 const float* __restrict__ be3,
                 const int* __restrict__ rowIdx, const int* __restrict__ colIdx) {
    extern __shared__ __align__(16) unsigned smem_u[];
    int* s_col = (int*)smem_u;
    int* s_row = s_col + 128;
    unsigned* sActs = smem_u + ACTS_OFF / 4;
    unsigned* sA8 = smem_u + A8_OFF / 4;

    unsigned sbase;
    asm("{ .reg .u64 t; cvta.to.shared.u64 t, %1; cvt.u32.u64 %0, t; }"
        : "=r"(sbase) : "l"(smem_u));
    const unsigned actsB = sbase + ACTS_OFF;
    const unsigned a8B = sbase + A8_OFF;
    const unsigned abufB[2] = {sbase + ABUF0_OFF, sbase + ABUF1_OFF};
    const unsigned bbufB[2] = {sbase + BBUF0_OFF, sbase + BBUF1_OFF};

    const __nv_bfloat16* W1 = &g_We1b[(size_t)layer * KE_PAD * H];
    const __nv_bfloat16* W2 = &g_We2b[(size_t)layer * H * H];
    const __nv_bfloat16* W3 = &g_We3b[(size_t)layer * H * H];

    int tid = threadIdx.x;
    int eb = blockIdx.x * BM;

    if (tid < 128) s_col[tid] = colIdx[eb + tid];
    else           s_row[tid - 128] = rowIdx[eb + tid - 128];
    __syncthreads();

    int warp = tid >> 5, lane = tid & 31;
    int lr = lane >> 2, lc = lane & 3;
    int wm = (warp & 1) * 64;
    int wn = (warp >> 1) * 32;

    int rA = tid >> 1, halfA = tid & 1;   // A staging: row, 32B half
    int rB = tid >> 3;                    // B staging: row
    int cB = (tid & 7) * 16;              // B staging: col (bf16)

    // ---- pre-stage chunk 8 A data (ea + rel_mom), pitch 48B
    if (tid < 128) {
        int r = tid;
        float4 ea = *(const float4*)&g_ea[(eb + r) * 4];
        int ci = s_col[r] * H, ri = s_row[r] * H;
        float rm0 = g_h[ci + 3] - g_h[ri + 3];
        float rm1 = g_h[ci + 4] - g_h[ri + 4];
        float rm2 = g_h[ci + 5] - g_h[ri + 5];
        unsigned* dst = &sA8[r * 12];
        dst[0] = pack_bf2(ea.x, ea.y);
        dst[1] = pack_bf2(ea.z, ea.w);
        dst[2] = pack_bf2(rm0, rm1);
        dst[3] = pack_bf2(rm2, 0.f);
        dst[4] = 0u; dst[5] = 0u; dst[6] = 0u; dst[7] = 0u;
    }

    float d[4][4][4];
#pragma unroll
    for (int mt = 0; mt < 4; mt++)
#pragma unroll
        for (int nt = 0; nt < 4; nt++)
#pragma unroll
            for (int i = 0; i < 4; i++) d[mt][nt][i] = 0.f;

    // ---- issue helpers
    auto issueA = [&](int ch, int p) {
        int node = (ch < 4) ? s_col[rA] : s_row[rA];
        int kbase = (ch & 3) * 32;
        cp16x2(abufB[p] + rA * 80 + halfA * 32,
               &g_hb[(size_t)node * H + kbase + halfA * 16]);
    };
    auto issueB = [&](const __nv_bfloat16* Wb, int ch, int p) {
        cp16x2(bbufB[p] + rB * 272 + cB * 2,
               &Wb[(size_t)(ch * 32 + rB) * H + cB]);
    };

    // ================= GEMM1: K = 288 (padded), 9 chunks of 32
    issueA(0, 0);
    issueB(W1, 0, 0);
    CP_COMMIT;

    for (int ch = 0; ch <= 8; ch++) {
        int p = ch & 1;
        if (ch < 8) {
            int p1 = (ch + 1) & 1;
            if (ch + 1 < 8) issueA(ch + 1, p1);
            issueB(W1, ch + 1, p1);
            CP_COMMIT;
            CP_WAIT1;
        } else {
            CP_WAIT0;
        }
        __syncthreads();
        int nk16 = (ch < 8) ? 2 : 1;
        for (int k16 = 0; k16 < nk16; k16++) {
            int k0 = k16 * 16;
            unsigned a[4][4], b[4][2];
            if (ch < 8) {
#pragma unroll
                for (int mt = 0; mt < 4; mt++)
                    ldsm_x4(a[mt][0], a[mt][1], a[mt][2], a[mt][3],
                            abufB[p] + (wm + mt * 16 + (lane & 15)) * 80
                                     + (k0 + ((lane >> 4) << 3)) * 2);
            } else {
#pragma unroll
                for (int mt = 0; mt < 4; mt++)
                    ldsm_x4(a[mt][0], a[mt][1], a[mt][2], a[mt][3],
                            a8B + (wm + mt * 16 + (lane & 15)) * 48
                                + ((lane >> 4) << 3) * 2);
            }
#pragma unroll
            for (int np = 0; np < 2; np++)
                ldsm_x4t(b[2 * np][0], b[2 * np][1], b[2 * np + 1][0], b[2 * np + 1][1],
                         bbufB[p] + (k0 + (lane & 7) + (lane & 8)) * 272
                                  + (wn + np * 16 + ((lane >> 4) << 3)) * 2);
#pragma unroll
            for (int mt = 0; mt < 4; mt++)
#pragma unroll
                for (int nt = 0; nt < 4; nt++) mma_bf16(d[mt][nt], a[mt], b[nt]);
        }
        __syncthreads();
    }

    // prefetch GEMM2 chunk 0 (Bbuf[0] free: last read at chunk 8, synced)
    issueB(W2, 0, 0);
    CP_COMMIT;

    // epilogue1: bias + relu -> acts
#pragma unroll
    for (int mt = 0; mt < 4; mt++)
#pragma unroll
        for (int nt = 0; nt < 4; nt++) {
            int row = wm + mt * 16 + lr;
            int col = wn + nt * 8 + 2 * lc;
            float2 bv = *(const float2*)&be1[col];
            sActs[(row * 136 + col) >> 1] =
                pack_bf2(fmaxf(d[mt][nt][0] + bv.x, 0.f), fmaxf(d[mt][nt][1] + bv.y, 0.f));
            sActs[((row + 8) * 136 + col) >> 1] =
                pack_bf2(fmaxf(d[mt][nt][2] + bv.x, 0.f), fmaxf(d[mt][nt][3] + bv.y, 0.f));
        }

    // ================= GEMM2: acts @ We2, K = 128, 4 chunks
#pragma unroll
    for (int mt = 0; mt < 4; mt++)
#pragma unroll
        for (int nt = 0; nt < 4; nt++)
#pragma unroll
            for (int i = 0; i < 4; i++) d[mt][nt][i] = 0.f;

    for (int ch = 0; ch < 4; ch++) {
        int p = ch & 1;
        if (ch < 3) {
            issueB(W2, ch + 1, (ch + 1) & 1);
            CP_COMMIT;
            CP_WAIT1;
        } else {
            CP_WAIT0;
        }
        __syncthreads();
#pragma unroll
        for (int k16 = 0; k16 < 2; k16++) {
            int kg = ch * 32 + k16 * 16;
            int k0 = k16 * 16;
            unsigned a[4][4], b[4][2];
#pragma unroll
            for (int mt = 0; mt < 4; mt++)
                ldsm_x4(a[mt][0], a[mt][1], a[mt][2], a[mt][3],
                        actsB + (wm + mt * 16 + (lane & 15)) * 272
                              + (kg + ((lane >> 4) << 3)) * 2);
#pragma unroll
            for (int np = 0; np < 2; np++)
                ldsm_x4t(b[2 * np][0], b[2 * np][1], b[2 * np + 1][0], b[2 * np + 1][1],
                         bbufB[p] + (k0 + (lane & 7) + (lane & 8)) * 272
                                  + (wn + np * 16 + ((lane >> 4) << 3)) * 2);
#pragma unroll
            for (int mt = 0; mt < 4; mt++)
#pragma unroll
                for (int nt = 0; nt < 4; nt++) mma_bf16(d[mt][nt], a[mt], b[nt]);
        }
        __syncthreads();
    }

    // prefetch GEMM3 chunk 0 (Bbuf[0] last read at GEMM2 chunk 2, synced)
    issueB(W3, 0, 0);
    CP_COMMIT;

    // epilogue2: bias + relu -> acts (in place; all GEMM2 reads done)
#pragma unroll
    for (int mt = 0; mt < 4; mt++)
#pragma unroll
        for (int nt = 0; nt < 4; nt++) {
            int row = wm + mt * 16 + lr;
            int col = wn + nt * 8 + 2 * lc;
            float2 bv = *(const float2*)&be2[col];
            sActs[(row * 136 + col) >> 1] =
                pack_bf2(fmaxf(d[mt][nt][0] + bv.x, 0.f), fmaxf(d[mt][nt][1] + bv.y, 0.f));
            sActs[((row + 8) * 136 + col) >> 1] =
                pack_bf2(fmaxf(d[mt][nt][2] + bv.x, 0.f), fmaxf(d[mt][nt][3] + bv.y, 0.f));
        }

    // ================= GEMM3: acts @ We3, K = 128 -> scatter
#pragma unroll
    for (int mt = 0; mt < 4; mt++)
#pragma unroll
        for (int nt = 0; nt < 4; nt++)
#pragma unroll
            for (int i = 0; i < 4; i++) d[mt][nt][i] = 0.f;

    for (int ch = 0; ch < 4; ch++) {
        int p = ch & 1;
        if (ch < 3) {
            issueB(W3, ch + 1, (ch + 1) & 1);
            CP_COMMIT;
            CP_WAIT1;
        } else {
            CP_WAIT0;
        }
        __syncthreads();
#pragma unroll
        for (int k16 = 0; k16 < 2; k16++) {
            int kg = ch * 32 + k16 * 16;
            int k0 = k16 * 16;
            unsigned a[4][4], b[4][2];
#pragma unroll
            for (int mt = 0; mt < 4; mt++)
                ldsm_x4(a[mt][0], a[mt][1], a[mt][2], a[mt][3],
                        actsB + (wm + mt * 16 + (lane & 15)) * 272
                              + (kg + ((lane >> 4) << 3)) * 2);
#pragma unroll
            for (int np = 0; np < 2; np++)
                ldsm_x4t(b[2 * np][0], b[2 * np][1], b[2 * np + 1][0], b[2 * np + 1][1],
                         bbufB[p] + (k0 + (lane & 7) + (lane & 8)) * 272
                                  + (wn + np * 16 + ((lane >> 4) << 3)) * 2);
#pragma unroll
            for (int mt = 0; mt < 4; mt++)
#pragma unroll
                for (int nt = 0; nt < 4; nt++) mma_bf16(d[mt][nt], a[mt], b[nt]);
        }
        __syncthreads();
    }

    // epilogue3: bias + scatter red.add
#pragma unroll
    for (int mt = 0; mt < 4; mt++)
#pragma unroll
        for (int nt = 0; nt < 4; nt++) {
            int e0 = wm + mt * 16 + lr;
            int col = wn + nt * 8 + 2 * lc;
            float2 bv = *(const float2*)&be3[col];
            int t0 = s_col[e0], t1 = s_col[e0 + 8];
            red_add_f2(&g_agg[t0 * H + col], d[mt][nt][0] + bv.x, d[mt][nt][1] + bv.y);
            red_add_f2(&g_agg[t1 * H + col], d[mt][nt][2] + bv.x, d[mt][nt][3] + bv.y);
        }
}

// ---------------------------------------------------------------- node MLP + residual + LN (fp32)
__global__ __launch_bounds__(256, 2)
void node_kernel(const float* __restrict__ Wn1, const float* __restrict__ bn1,
                 const float* __restrict__ Wn2, const float* __restrict__ bn2,
                 const float* __restrict__ Wn3, const float* __restrict__ bn3,
                 const float* __restrict__ lng, const float* __restrict__ lnb,
                 float* __restrict__ out) {
    extern __shared__ float smem[];
    float* As = smem;
    float* Bs = As + BM * BK;
    float* acts = Bs + BK * H;

    int tid = threadIdx.x;
    int nb = blockIdx.x * BM;
    int tx = tid & 15, ty = tid >> 4;
    int le = tid >> 1;
    int lk = (tid & 1) * 4;
    int wk = tid >> 5;
    int wn = (tid & 31) * 4;

    float c[8][8];
#pragma unroll
    for (int i = 0; i < 8; i++)
#pragma unroll
        for (int j = 0; j < 8; j++) c[i][j] = 0.f;

    for (int kk = 0; kk < KN; kk += BK) {
        int node = nb + le;
        float4 av = make_float4(0.f, 0.f, 0.f, 0.f);
        if (node < N_NODES) {
            if (kk < 128) av = *(const float4*)&g_h[node * H + kk + lk];
            else          av = *(const float4*)&g_agg[node * H + (kk - 128) + lk];
        }
        *(float4*)&As[le * BK + lk] = av;
        *(float4*)&Bs[wk * H + wn] = *(const float4*)&Wn1[(kk + wk) * H + wn];
        __syncthreads();
#pragma unroll
        for (int k = 0; k < BK; k++) {
            float a[8];
#pragma unroll
            for (int i = 0; i < 8; i++) a[i] = As[(ty * 8 + i) * BK + k];
            float4 b0 = *(float4*)&Bs[k * H + tx * 8];
            float4 b1 = *(float4*)&Bs[k * H + tx * 8 + 4];
            float bb[8] = {b0.x, b0.y, b0.z, b0.w, b1.x, b1.y, b1.z, b1.w};
#pragma unroll
            for (int i = 0; i < 8; i++)
#pragma unroll
                for (int j = 0; j < 8; j++) c[i][j] += a[i] * bb[j];
        }
        __syncthreads();
    }
    {
        float4 t0 = *(const float4*)&bn1[tx * 8];
        float4 t1 = *(const float4*)&bn1[tx * 8 + 4];
        float bias[8] = {t0.x, t0.y, t0.z, t0.w, t1.x, t1.y, t1.z, t1.w};
#pragma unroll
        for (int i = 0; i < 8; i++) {
            float4 v0, v1;
            v0.x = fmaxf(c[i][0] + bias[0], 0.f); v0.y = fmaxf(c[i][1] + bias[1], 0.f);
            v0.z = fmaxf(c[i][2] + bias[2], 0.f); v0.w = fmaxf(c[i][3] + bias[3], 0.f);
            v1.x = fmaxf(c[i][4] + bias[4], 0.f); v1.y = fmaxf(c[i][5] + bias[5], 0.f);
            v1.z = fmaxf(c[i][6] + bias[6], 0.f); v1.w = fmaxf(c[i][7] + bias[7], 0.f);
            *(float4*)&acts[(ty * 8 + i) * AP + tx * 8] = v0;
            *(float4*)&acts[(ty * 8 + i) * AP + tx * 8 + 4] = v1;
        }
    }
    __syncthreads();

#pragma unroll
    for (int i = 0; i < 8; i++)
#pragma unroll
        for (int j = 0; j < 8; j++) c[i][j] = 0.f;
    for (int kk = 0; kk < H; kk += BK) {
        *(float4*)&Bs[wk * H + wn] = *(const float4*)&Wn2[(kk + wk) * H + wn];
        __syncthreads();
#pragma unroll
        for (int k = 0; k < BK; k++) {
            float a[8];
#pragma unroll
            for (int i = 0; i < 8; i++) a[i] = acts[(ty * 8 + i) * AP + kk + k];
            float4 b0 = *(float4*)&Bs[k * H + tx * 8];
            float4 b1 = *(float4*)&Bs[k * H + tx * 8 + 4];
            float bb[8] = {b0.x, b0.y, b0.z, b0.w, b1.x, b1.y, b1.z, b1.w};
#pragma unroll
            for (int i = 0; i < 8; i++)
#pragma unroll
                for (int j = 0; j < 8; j++) c[i][j] += a[i] * bb[j];
        }
        __syncthreads();
    }
    {
        float4 t0 = *(const float4*)&bn2[tx * 8];
        float4 t1 = *(const float4*)&bn2[tx * 8 + 4];
        float bias[8] = {t0.x, t0.y, t0.z, t0.w, t1.x, t1.y, t1.z, t1.w};
        float m2[8][8];
#pragma unroll
        for (int i = 0; i < 8; i++)
#pragma unroll
            for (int j = 0; j < 8; j++) m2[i][j] = fmaxf(c[i][j] + bias[j], 0.f);
        __syncthreads();
#pragma unroll
        for (int i = 0; i < 8; i++) {
            *(float4*)&acts[(ty * 8 + i) * AP + tx * 8]     = make_float4(m2[i][0], m2[i][1], m2[i][2], m2[i][3]);
            *(float4*)&acts[(ty * 8 + i) * AP + tx * 8 + 4] = make_float4(m2[i][4], m2[i][5], m2[i][6], m2[i][7]);
        }
    }
    __syncthreads();

#pragma unroll
    for (int i = 0; i < 8; i++)
#pragma unroll
        for (int j = 0; j < 8; j++) c[i][j] = 0.f;
    for (int kk = 0; kk < H; kk += BK) {
        *(float4*)&Bs[wk * H + wn] = *(const float4*)&Wn3[(kk + wk) * H + wn];
        __syncthreads();
#pragma unroll
        for (int k = 0; k < BK; k++) {
            float a[8];
#pragma unroll
            for (int i = 0; i < 8; i++) a[i] = acts[(ty * 8 + i) * AP + kk + k];
            float4 b0 = *(float4*)&Bs[k * H + tx * 8];
            float4 b1 = *(float4*)&Bs[k * H + tx * 8 + 4];
            float bb[8] = {b0.x, b0.y, b0.z, b0.w, b1.x, b1.y, b1.z, b1.w};
#pragma unroll
            for (int i = 0; i < 8; i++)
#pragma unroll
                for (int j = 0; j < 8; j++) c[i][j] += a[i] * bb[j];
        }
        __syncthreads();
    }
    {
        float4 t0 = *(const float4*)&bn3[tx * 8];
        float4 t1 = *(const float4*)&bn3[tx * 8 + 4];
        float bias[8] = {t0.x, t0.y, t0.z, t0.w, t1.x, t1.y, t1.z, t1.w};
#pragma unroll
        for (int i = 0; i < 8; i++) {
            int node = nb + ty * 8 + i;
            float4 h0 = make_float4(0.f, 0.f, 0.f, 0.f), h1 = make_float4(0.f, 0.f, 0.f, 0.f);
            if (node < N_NODES) {
                h0 = *(const float4*)&g_h[node * H + tx * 8];
                h1 = *(const float4*)&g_h[node * H + tx * 8 + 4];
            }
            *(float4*)&acts[(ty * 8 + i) * AP + tx * 8] =
                make_float4(h0.x + c[i][0] + bias[0], h0.y + c[i][1] + bias[1],
                            h0.z + c[i][2] + bias[2], h0.w + c[i][3] + bias[3]);
            *(float4*)&acts[(ty * 8 + i) * AP + tx * 8 + 4] =
                make_float4(h1.x + c[i][4] + bias[4], h1.y + c[i][5] + bias[5],
                            h1.z + c[i][6] + bias[6], h1.w + c[i][7] + bias[7]);
        }
    }
    __syncthreads();

    {
        int lane = tid & 31, warp = tid >> 5;
        for (int r = warp * 16; r < warp * 16 + 16; r++) {
            int node = nb + r;
            float v0 = acts[r * AP + lane];
            float v1 = acts[r * AP + lane + 32];
            float v2 = acts[r * AP + lane + 64];
            float v3 = acts[r * AP + lane + 96];
            float s = v0 + v1 + v2 + v3;
            float q = v0 * v0 + v1 * v1 + v2 * v2 + v3 * v3;
#pragma unroll
            for (int off = 16; off > 0; off >>= 1) {
                s += __shfl_xor_sync(0xffffffffu, s, off);
                q += __shfl_xor_sync(0xffffffffu, q, off);
            }
            float mean = s * (1.f / 128.f);
            float var = q * (1.f / 128.f) - mean * mean;
            float rstd = rsqrtf(var + 1e-5f);
            if (node < N_NODES) {
                float o0 = (v0 - mean) * rstd * lng[lane]      + lnb[lane];
                float o1 = (v1 - mean) * rstd * lng[lane + 32] + lnb[lane + 32];
                float o2 = (v2 - mean) * rstd * lng[lane + 64] + lnb[lane + 64];
                float o3 = (v3 - mean) * rstd * lng[lane + 96] + lnb[lane + 96];
                out[node * H + lane]      = o0;
                out[node * H + lane + 32] = o1;
                out[node * H + lane + 64] = o2;
                out[node * H + lane + 96] = o3;
                g_hb[node * H + lane]      = __float2bfloat16(o0);
                g_hb[node * H + lane + 32] = __float2bfloat16(o1);
                g_hb[node * H + lane + 64] = __float2bfloat16(o2);
                g_hb[node * H + lane + 96] = __float2bfloat16(o3);
            }
        }
    }
}

// ----------------------------------------------------------------
extern "C" void kernel_launch(void* const* d_in, const int* in_sizes, int n_in,
                              void* d_out, int out_size) {
    const float* x    = (const float*)d_in[0];
    const float* pos  = (const float*)d_in[1];
    const int*   ei   = (const int*)d_in[2];
    const float* W_in = (const float*)d_in[3];
    const float* b_in = (const float*)d_in[4];
    const float* We1  = (const float*)d_in[5];
    const float* be1  = (const float*)d_in[6];
    const float* We2  = (const float*)d_in[7];
    const float* be2  = (const float*)d_in[8];
    const float* We3  = (const float*)d_in[9];
    const float* be3  = (const float*)d_in[10];
    const float* Wn1  = (const float*)d_in[11];
    const float* bn1  = (const float*)d_in[12];
    const float* Wn2  = (const float*)d_in[13];
    const float* bn2  = (const float*)d_in[14];
    const float* Wn3  = (const float*)d_in[15];
    const float* bn3  = (const float*)d_in[16];
    const float* ln_g = (const float*)d_in[17];
    const float* ln_b = (const float*)d_in[18];

    const int* rowIdx = ei;
    const int* colIdx = ei + N_EDGES;

    size_t smem_edge = SMEM_EDGE;
    size_t smem_node = (size_t)(BM * BK + BK * H + BM * AP) * sizeof(float);
    cudaFuncSetAttribute(edge_kernel, cudaFuncAttributeMaxDynamicSharedMemorySize, (int)smem_edge);
    cudaFuncSetAttribute(node_kernel, cudaFuncAttributeMaxDynamicSharedMemorySize, (int)smem_node);

    float* hptr = nullptr;
    cudaGetSymbolAddress((void**)&hptr, g_h);

    int prep_total = LAYERS * KE_PAD * H + 2 * LAYERS * H * H;
    prep_weights<<<(prep_total + 255) / 256, 256>>>(We1, We2, We3);
    embed_kernel<<<(N_NODES * H + 255) / 256, 256>>>(x, W_in, b_in);
    ea_kernel<<<(N_EDGES + 255) / 256, 256>>>(pos, rowIdx, colIdx);

    int edge_blocks = N_EDGES / BM;
    int node_blocks = (N_NODES + BM - 1) / BM;
    int zero_blocks = (N_NODES * H / 4) / 256;

    for (int l = 0; l < LAYERS; l++) {
        zero_agg_kernel<<<zero_blocks, 256>>>();
        edge_kernel<<<edge_blocks, 256, smem_edge>>>(
            l, be1 + l * H, be2 + l * H, be3 + l * H, rowIdx, colIdx);
        float* outp = (l == LAYERS - 1) ? (float*)d_out : hptr;
        node_kernel<<<node_blocks, 256, smem_node>>>(
            Wn1 + (size_t)l * KN * H, bn1 + l * H,
            Wn2 + (size_t)l * H * H,  bn2 + l * H,
            Wn3 + (size_t)l * H * H,  bn3 + l * H,
            ln_g + l * H, ln_b + l * H, outp);
    }
}

// round 5
// speedup vs baseline: 6.2100x; 1.3278x over previous
#include <cuda_runtime.h>
#include <cuda_bf16.h>
#include <math.h>

#define N_NODES 50000
#define N_EDGES 800000
#define H 128
#define LAYERS 4
#define KE 263
#define KN 256
#define BM 128
#define KE_PAD 288

// edge smem layout (bytes)
#define ACTS_OFF  1024
#define A8_OFF    35840
#define ABUF0_OFF 41984
#define ABUF1_OFF 52224
#define BBUF0_OFF 62464
#define BBUF1_OFF 71168
#define SMEM_EDGE 79872

// node smem layout (bytes): LN fp32 buffer [1024, 68608) aliases everything below
#define NACTS_OFF  1024
#define NABUF0_OFF 35840
#define NABUF1_OFF 46080
#define NBBUF0_OFF 56320
#define NBBUF1_OFF 65024
#define SMEM_NODE  73728
#define NLN_OFF    1024

__device__ float g_h[N_NODES * H];
__device__ float g_agg[N_NODES * H];
__device__ float g_ea[N_EDGES * 4];
__device__ __nv_bfloat16 g_hb[N_NODES * H];
__device__ __nv_bfloat16 g_aggb[N_NODES * H];
__device__ __nv_bfloat16 g_We1b[LAYERS * KE_PAD * H];
__device__ __nv_bfloat16 g_We2b[LAYERS * H * H];
__device__ __nv_bfloat16 g_We3b[LAYERS * H * H];
__device__ __nv_bfloat16 g_Wn1b[LAYERS * KN * H];
__device__ __nv_bfloat16 g_Wn2b[LAYERS * H * H];
__device__ __nv_bfloat16 g_Wn3b[LAYERS * H * H];

#define CP_COMMIT asm volatile("cp.async.commit_group;" ::: "memory")
#define CP_WAIT1  asm volatile("cp.async.wait_group 1;" ::: "memory")
#define CP_WAIT0  asm volatile("cp.async.wait_group 0;" ::: "memory")

__device__ __forceinline__ void cp16x2(unsigned dst, const void* src) {
    asm volatile("cp.async.cg.shared.global [%0], [%1], 16;\n\t"
                 "cp.async.cg.shared.global [%2], [%3], 16;"
                 :: "r"(dst), "l"(src), "r"(dst + 16), "l"((const char*)src + 16) : "memory");
}

__device__ __forceinline__ void red_add_f2(float* p, float a, float b) {
    asm volatile("red.global.add.v2.f32 [%0], {%1,%2};"
                 :: "l"(p), "f"(a), "f"(b) : "memory");
}

__device__ __forceinline__ unsigned pack_bf2(float lo, float hi) {
    __nv_bfloat162 v = __floats2bfloat162_rn(lo, hi);
    return *(unsigned*)&v;
}

__device__ __forceinline__ void ldsm_x4(unsigned& r0, unsigned& r1, unsigned& r2, unsigned& r3,
                                        unsigned addr) {
    asm volatile("ldmatrix.sync.aligned.m8n8.x4.shared.b16 {%0,%1,%2,%3}, [%4];"
                 : "=r"(r0), "=r"(r1), "=r"(r2), "=r"(r3) : "r"(addr));
}

__device__ __forceinline__ void ldsm_x4t(unsigned& r0, unsigned& r1, unsigned& r2, unsigned& r3,
                                         unsigned addr) {
    asm volatile("ldmatrix.sync.aligned.m8n8.x4.trans.shared.b16 {%0,%1,%2,%3}, [%4];"
                 : "=r"(r0), "=r"(r1), "=r"(r2), "=r"(r3) : "r"(addr));
}

__device__ __forceinline__ void mma_bf16(float d[4], const unsigned a[4], const unsigned b[2]) {
    asm volatile("mma.sync.aligned.m16n8k16.row.col.f32.bf16.bf16.f32 "
                 "{%0,%1,%2,%3}, {%4,%5,%6,%7}, {%8,%9}, {%0,%1,%2,%3};"
                 : "+f"(d[0]), "+f"(d[1]), "+f"(d[2]), "+f"(d[3])
                 : "r"(a[0]), "r"(a[1]), "r"(a[2]), "r"(a[3]), "r"(b[0]), "r"(b[1]));
}

// ---------------------------------------------------------------- weight prep (fp32 -> bf16)
__global__ void prep_weights(const float* __restrict__ We1,
                             const float* __restrict__ We2,
                             const float* __restrict__ We3,
                             const float* __restrict__ Wn1,
                             const float* __restrict__ Wn2,
                             const float* __restrict__ Wn3) {
    int id = blockIdx.x * blockDim.x + threadIdx.x;
    const int n1 = LAYERS * KE_PAD * H;
    const int n2 = LAYERS * H * H;
    const int n3 = LAYERS * KN * H;
    if (id < n1) {
        int l = id / (KE_PAD * H);
        int rem = id % (KE_PAD * H);
        int r = rem / H, c = rem % H;
        float v = (r < KE) ? We1[((size_t)l * KE + r) * H + c] : 0.f;
        g_We1b[id] = __float2bfloat16(v);
    } else if (id < n1 + n2) {
        g_We2b[id - n1] = __float2bfloat16(We2[id - n1]);
    } else if (id < n1 + 2 * n2) {
        g_We3b[id - n1 - n2] = __float2bfloat16(We3[id - n1 - n2]);
    } else if (id < n1 + 2 * n2 + n3) {
        int k = id - n1 - 2 * n2;
        g_Wn1b[k] = __float2bfloat16(Wn1[k]);
    } else if (id < n1 + 2 * n2 + n3 + n2) {
        int k = id - n1 - 2 * n2 - n3;
        g_Wn2b[k] = __float2bfloat16(Wn2[k]);
    } else if (id < n1 + 2 * n2 + n3 + 2 * n2) {
        int k = id - n1 - 2 * n2 - n3 - n2;
        g_Wn3b[k] = __float2bfloat16(Wn3[k]);
    }
}

// ---------------------------------------------------------------- embed
__global__ void embed_kernel(const float* __restrict__ x,
                             const float* __restrict__ W,
                             const float* __restrict__ b) {
    int gid = blockIdx.x * blockDim.x + threadIdx.x;
    if (gid >= N_NODES * H) return;
    int i = gid >> 7;
    int j = gid & (H - 1);
    const float* xr = x + i * 16;
    float acc = b[j];
#pragma unroll
    for (int k = 0; k < 16; k++) acc += xr[k] * W[k * H + j];
    g_h[gid] = acc;
    g_hb[gid] = __float2bfloat16(acc);
}

// ---------------------------------------------------------------- edge_attr
__global__ void ea_kernel(const float* __restrict__ pos,
                          const int* __restrict__ rowIdx,
                          const int* __restrict__ colIdx) {
    int e = blockIdx.x * blockDim.x + threadIdx.x;
    if (e >= N_EDGES) return;
    int r = rowIdx[e], c = colIdx[e];
    float dx = pos[c * 3 + 0] - pos[r * 3 + 0];
    float dy = pos[c * 3 + 1] - pos[r * 3 + 1];
    float dz = pos[c * 3 + 2] - pos[r * 3 + 2];
    float d = sqrtf(dx * dx + dy * dy + dz * dz);
    *(float4*)&g_ea[e * 4] = make_float4(dx, dy, dz, d);
}

__global__ void zero_agg_kernel() {
    int gid = blockIdx.x * blockDim.x + threadIdx.x;
    ((float4*)g_agg)[gid] = make_float4(0.f, 0.f, 0.f, 0.f);
}

// ---------------------------------------------------------------- agg fp32 -> bf16 mirror
__global__ void cvt_agg_kernel() {
    int gid = blockIdx.x * blockDim.x + threadIdx.x;   // N*H/8 threads
    const float4* src = (const float4*)g_agg;
    float4 a = src[2 * gid];
    float4 b = src[2 * gid + 1];
    uint4 o;
    o.x = pack_bf2(a.x, a.y);
    o.y = pack_bf2(a.z, a.w);
    o.z = pack_bf2(b.x, b.y);
    o.w = pack_bf2(b.z, b.w);
    ((uint4*)g_aggb)[gid] = o;
}

// ---------------------------------------------------------------- fused edge MLP: cp.async pipelined bf16 mma
__global__ __launch_bounds__(256, 2)
void edge_kernel(int layer,
                 const float* __restrict__ be1, const float* __restrict__ be2,
                 const float* __restrict__ be3,
                 const int* __restrict__ rowIdx, const int* __restrict__ colIdx) {
    extern __shared__ __align__(16) unsigned smem_u[];
    int* s_col = (int*)smem_u;
    int* s_row = s_col + 128;
    unsigned* sActs = smem_u + ACTS_OFF / 4;
    unsigned* sA8 = smem_u + A8_OFF / 4;

    unsigned sbase;
    asm("{ .reg .u64 t; cvta.to.shared.u64 t, %1; cvt.u32.u64 %0, t; }"
        : "=r"(sbase) : "l"(smem_u));
    const unsigned actsB = sbase + ACTS_OFF;
    const unsigned a8B = sbase + A8_OFF;
    const unsigned abufB[2] = {sbase + ABUF0_OFF, sbase + ABUF1_OFF};
    const unsigned bbufB[2] = {sbase + BBUF0_OFF, sbase + BBUF1_OFF};

    const __nv_bfloat16* W1 = &g_We1b[(size_t)layer * KE_PAD * H];
    const __nv_bfloat16* W2 = &g_We2b[(size_t)layer * H * H];
    const __nv_bfloat16* W3 = &g_We3b[(size_t)layer * H * H];

    int tid = threadIdx.x;
    int eb = blockIdx.x * BM;

    if (tid < 128) s_col[tid] = colIdx[eb + tid];
    else           s_row[tid - 128] = rowIdx[eb + tid - 128];
    __syncthreads();

    int warp = tid >> 5, lane = tid & 31;
    int lr = lane >> 2, lc = lane & 3;
    int wm = (warp & 1) * 64;
    int wn = (warp >> 1) * 32;

    int rA = tid >> 1, halfA = tid & 1;
    int rB = tid >> 3;
    int cB = (tid & 7) * 16;

    if (tid < 128) {
        int r = tid;
        float4 ea = *(const float4*)&g_ea[(eb + r) * 4];
        int ci = s_col[r] * H, ri = s_row[r] * H;
        float rm0 = g_h[ci + 3] - g_h[ri + 3];
        float rm1 = g_h[ci + 4] - g_h[ri + 4];
        float rm2 = g_h[ci + 5] - g_h[ri + 5];
        unsigned* dst = &sA8[r * 12];
        dst[0] = pack_bf2(ea.x, ea.y);
        dst[1] = pack_bf2(ea.z, ea.w);
        dst[2] = pack_bf2(rm0, rm1);
        dst[3] = pack_bf2(rm2, 0.f);
        dst[4] = 0u; dst[5] = 0u; dst[6] = 0u; dst[7] = 0u;
    }

    float d[4][4][4];
#pragma unroll
    for (int mt = 0; mt < 4; mt++)
#pragma unroll
        for (int nt = 0; nt < 4; nt++)
#pragma unroll
            for (int i = 0; i < 4; i++) d[mt][nt][i] = 0.f;

    auto issueA = [&](int ch, int p) {
        int node = (ch < 4) ? s_col[rA] : s_row[rA];
        int kbase = (ch & 3) * 32;
        cp16x2(abufB[p] + rA * 80 + halfA * 32,
               &g_hb[(size_t)node * H + kbase + halfA * 16]);
    };
    auto issueB = [&](const __nv_bfloat16* Wb, int ch, int p) {
        cp16x2(bbufB[p] + rB * 272 + cB * 2,
               &Wb[(size_t)(ch * 32 + rB) * H + cB]);
    };

    // ===== GEMM1: K = 288 padded (9 chunks)
    issueA(0, 0);
    issueB(W1, 0, 0);
    CP_COMMIT;

    for (int ch = 0; ch <= 8; ch++) {
        int p = ch & 1;
        if (ch < 8) {
            int p1 = (ch + 1) & 1;
            if (ch + 1 < 8) issueA(ch + 1, p1);
            issueB(W1, ch + 1, p1);
            CP_COMMIT;
            CP_WAIT1;
        } else {
            CP_WAIT0;
        }
        __syncthreads();
        int nk16 = (ch < 8) ? 2 : 1;
        for (int k16 = 0; k16 < nk16; k16++) {
            int k0 = k16 * 16;
            unsigned a[4][4], b[4][2];
            if (ch < 8) {
#pragma unroll
                for (int mt = 0; mt < 4; mt++)
                    ldsm_x4(a[mt][0], a[mt][1], a[mt][2], a[mt][3],
                            abufB[p] + (wm + mt * 16 + (lane & 15)) * 80
                                     + (k0 + ((lane >> 4) << 3)) * 2);
            } else {
#pragma unroll
                for (int mt = 0; mt < 4; mt++)
                    ldsm_x4(a[mt][0], a[mt][1], a[mt][2], a[mt][3],
                            a8B + (wm + mt * 16 + (lane & 15)) * 48
                                + ((lane >> 4) << 3) * 2);
            }
#pragma unroll
            for (int np = 0; np < 2; np++)
                ldsm_x4t(b[2 * np][0], b[2 * np][1], b[2 * np + 1][0], b[2 * np + 1][1],
                         bbufB[p] + (k0 + (lane & 7) + (lane & 8)) * 272
                                  + (wn + np * 16 + ((lane >> 4) << 3)) * 2);
#pragma unroll
            for (int mt = 0; mt < 4; mt++)
#pragma unroll
                for (int nt = 0; nt < 4; nt++) mma_bf16(d[mt][nt], a[mt], b[nt]);
        }
        __syncthreads();
    }

    issueB(W2, 0, 0);
    CP_COMMIT;

#pragma unroll
    for (int mt = 0; mt < 4; mt++)
#pragma unroll
        for (int nt = 0; nt < 4; nt++) {
            int row = wm + mt * 16 + lr;
            int col = wn + nt * 8 + 2 * lc;
            float2 bv = *(const float2*)&be1[col];
            sActs[(row * 136 + col) >> 1] =
                pack_bf2(fmaxf(d[mt][nt][0] + bv.x, 0.f), fmaxf(d[mt][nt][1] + bv.y, 0.f));
            sActs[((row + 8) * 136 + col) >> 1] =
                pack_bf2(fmaxf(d[mt][nt][2] + bv.x, 0.f), fmaxf(d[mt][nt][3] + bv.y, 0.f));
        }

    // ===== GEMM2
#pragma unroll
    for (int mt = 0; mt < 4; mt++)
#pragma unroll
        for (int nt = 0; nt < 4; nt++)
#pragma unroll
            for (int i = 0; i < 4; i++) d[mt][nt][i] = 0.f;

    for (int ch = 0; ch < 4; ch++) {
        int p = ch & 1;
        if (ch < 3) {
            issueB(W2, ch + 1, (ch + 1) & 1);
            CP_COMMIT;
            CP_WAIT1;
        } else {
            CP_WAIT0;
        }
        __syncthreads();
#pragma unroll
        for (int k16 = 0; k16 < 2; k16++) {
            int kg = ch * 32 + k16 * 16;
            int k0 = k16 * 16;
            unsigned a[4][4], b[4][2];
#pragma unroll
            for (int mt = 0; mt < 4; mt++)
                ldsm_x4(a[mt][0], a[mt][1], a[mt][2], a[mt][3],
                        actsB + (wm + mt * 16 + (lane & 15)) * 272
                              + (kg + ((lane >> 4) << 3)) * 2);
#pragma unroll
            for (int np = 0; np < 2; np++)
                ldsm_x4t(b[2 * np][0], b[2 * np][1], b[2 * np + 1][0], b[2 * np + 1][1],
                         bbufB[p] + (k0 + (lane & 7) + (lane & 8)) * 272
                                  + (wn + np * 16 + ((lane >> 4) << 3)) * 2);
#pragma unroll
            for (int mt = 0; mt < 4; mt++)
#pragma unroll
                for (int nt = 0; nt < 4; nt++) mma_bf16(d[mt][nt], a[mt], b[nt]);
        }
        __syncthreads();
    }

    issueB(W3, 0, 0);
    CP_COMMIT;

#pragma unroll
    for (int mt = 0; mt < 4; mt++)
#pragma unroll
        for (int nt = 0; nt < 4; nt++) {
            int row = wm + mt * 16 + lr;
            int col = wn + nt * 8 + 2 * lc;
            float2 bv = *(const float2*)&be2[col];
            sActs[(row * 136 + col) >> 1] =
                pack_bf2(fmaxf(d[mt][nt][0] + bv.x, 0.f), fmaxf(d[mt][nt][1] + bv.y, 0.f));
            sActs[((row + 8) * 136 + col) >> 1] =
                pack_bf2(fmaxf(d[mt][nt][2] + bv.x, 0.f), fmaxf(d[mt][nt][3] + bv.y, 0.f));
        }

    // ===== GEMM3
#pragma unroll
    for (int mt = 0; mt < 4; mt++)
#pragma unroll
        for (int nt = 0; nt < 4; nt++)
#pragma unroll
            for (int i = 0; i < 4; i++) d[mt][nt][i] = 0.f;

    for (int ch = 0; ch < 4; ch++) {
        int p = ch & 1;
        if (ch < 3) {
            issueB(W3, ch + 1, (ch + 1) & 1);
            CP_COMMIT;
            CP_WAIT1;
        } else {
            CP_WAIT0;
        }
        __syncthreads();
#pragma unroll
        for (int k16 = 0; k16 < 2; k16++) {
            int kg = ch * 32 + k16 * 16;
            int k0 = k16 * 16;
            unsigned a[4][4], b[4][2];
#pragma unroll
            for (int mt = 0; mt < 4; mt++)
                ldsm_x4(a[mt][0], a[mt][1], a[mt][2], a[mt][3],
                        actsB + (wm + mt * 16 + (lane & 15)) * 272
                              + (kg + ((lane >> 4) << 3)) * 2);
#pragma unroll
            for (int np = 0; np < 2; np++)
                ldsm_x4t(b[2 * np][0], b[2 * np][1], b[2 * np + 1][0], b[2 * np + 1][1],
                         bbufB[p] + (k0 + (lane & 7) + (lane & 8)) * 272
                                  + (wn + np * 16 + ((lane >> 4) << 3)) * 2);
#pragma unroll
            for (int mt = 0; mt < 4; mt++)
#pragma unroll
                for (int nt = 0; nt < 4; nt++) mma_bf16(d[mt][nt], a[mt], b[nt]);
        }
        __syncthreads();
    }

#pragma unroll
    for (int mt = 0; mt < 4; mt++)
#pragma unroll
        for (int nt = 0; nt < 4; nt++) {
            int e0 = wm + mt * 16 + lr;
            int col = wn + nt * 8 + 2 * lc;
            float2 bv = *(const float2*)&be3[col];
            int t0 = s_col[e0], t1 = s_col[e0 + 8];
            red_add_f2(&g_agg[t0 * H + col], d[mt][nt][0] + bv.x, d[mt][nt][1] + bv.y);
            red_add_f2(&g_agg[t1 * H + col], d[mt][nt][2] + bv.x, d[mt][nt][3] + bv.y);
        }
}

// ---------------------------------------------------------------- node MLP (bf16 mma) + residual + LN
__global__ __launch_bounds__(256, 2)
void node_kernel(int layer,
                 const float* __restrict__ bn1, const float* __restrict__ bn2,
                 const float* __restrict__ bn3,
                 const float* __restrict__ lng, const float* __restrict__ lnb,
                 float* __restrict__ out) {
    extern __shared__ __align__(16) unsigned smem_u[];
    unsigned* sActs = smem_u + NACTS_OFF / 4;
    float* sLN = (float*)(smem_u + NLN_OFF / 4);

    unsigned sbase;
    asm("{ .reg .u64 t; cvta.to.shared.u64 t, %1; cvt.u32.u64 %0, t; }"
        : "=r"(sbase) : "l"(smem_u));
    const unsigned actsB = sbase + NACTS_OFF;
    const unsigned abufB[2] = {sbase + NABUF0_OFF, sbase + NABUF1_OFF};
    const unsigned bbufB[2] = {sbase + NBBUF0_OFF, sbase + NBBUF1_OFF};

    const __nv_bfloat16* W1 = &g_Wn1b[(size_t)layer * KN * H];
    const __nv_bfloat16* W2 = &g_Wn2b[(size_t)layer * H * H];
    const __nv_bfloat16* W3 = &g_Wn3b[(size_t)layer * H * H];

    int tid = threadIdx.x;
    int nb = blockIdx.x * BM;

    int warp = tid >> 5, lane = tid & 31;
    int lr = lane >> 2, lc = lane & 3;
    int wm = (warp & 1) * 64;
    int wn = (warp >> 1) * 32;

    int rA = tid >> 1, halfA = tid & 1;
    int rB = tid >> 3;
    int cB = (tid & 7) * 16;
    int nodeA = nb + rA; if (nodeA >= N_NODES) nodeA = N_NODES - 1;

    float d[4][4][4];
#pragma unroll
    for (int mt = 0; mt < 4; mt++)
#pragma unroll
        for (int nt = 0; nt < 4; nt++)
#pragma unroll
            for (int i = 0; i < 4; i++) d[mt][nt][i] = 0.f;

    auto issueA = [&](int ch, int p) {
        const __nv_bfloat16* src = (ch < 4)
            ? &g_hb[(size_t)nodeA * H + ch * 32 + halfA * 16]
            : &g_aggb[(size_t)nodeA * H + (ch - 4) * 32 + halfA * 16];
        cp16x2(abufB[p] + rA * 80 + halfA * 32, src);
    };
    auto issueB = [&](const __nv_bfloat16* Wb, int ch, int p) {
        cp16x2(bbufB[p] + rB * 272 + cB * 2,
               &Wb[(size_t)(ch * 32 + rB) * H + cB]);
    };

    // ===== GEMM1: [h | agg] @ Wn1, K = 256 (8 chunks)
    issueA(0, 0);
    issueB(W1, 0, 0);
    CP_COMMIT;

    for (int ch = 0; ch < 8; ch++) {
        int p = ch & 1;
        if (ch < 7) {
            int p1 = (ch + 1) & 1;
            issueA(ch + 1, p1);
            issueB(W1, ch + 1, p1);
            CP_COMMIT;
            CP_WAIT1;
        } else {
            CP_WAIT0;
        }
        __syncthreads();
#pragma unroll
        for (int k16 = 0; k16 < 2; k16++) {
            int k0 = k16 * 16;
            unsigned a[4][4], b[4][2];
#pragma unroll
            for (int mt = 0; mt < 4; mt++)
                ldsm_x4(a[mt][0], a[mt][1], a[mt][2], a[mt][3],
                        abufB[p] + (wm + mt * 16 + (lane & 15)) * 80
                                 + (k0 + ((lane >> 4) << 3)) * 2);
#pragma unroll
            for (int np = 0; np < 2; np++)
                ldsm_x4t(b[2 * np][0], b[2 * np][1], b[2 * np + 1][0], b[2 * np + 1][1],
                         bbufB[p] + (k0 + (lane & 7) + (lane & 8)) * 272
                                  + (wn + np * 16 + ((lane >> 4) << 3)) * 2);
#pragma unroll
            for (int mt = 0; mt < 4; mt++)
#pragma unroll
                for (int nt = 0; nt < 4; nt++) mma_bf16(d[mt][nt], a[mt], b[nt]);
        }
        __syncthreads();
    }

    issueB(W2, 0, 0);
    CP_COMMIT;

#pragma unroll
    for (int mt = 0; mt < 4; mt++)
#pragma unroll
        for (int nt = 0; nt < 4; nt++) {
            int row = wm + mt * 16 + lr;
            int col = wn + nt * 8 + 2 * lc;
            float2 bv = *(const float2*)&bn1[col];
            sActs[(row * 136 + col) >> 1] =
                pack_bf2(fmaxf(d[mt][nt][0] + bv.x, 0.f), fmaxf(d[mt][nt][1] + bv.y, 0.f));
            sActs[((row + 8) * 136 + col) >> 1] =
                pack_bf2(fmaxf(d[mt][nt][2] + bv.x, 0.f), fmaxf(d[mt][nt][3] + bv.y, 0.f));
        }

    // ===== GEMM2
#pragma unroll
    for (int mt = 0; mt < 4; mt++)
#pragma unroll
        for (int nt = 0; nt < 4; nt++)
#pragma unroll
            for (int i = 0; i < 4; i++) d[mt][nt][i] = 0.f;

    for (int ch = 0; ch < 4; ch++) {
        int p = ch & 1;
        if (ch < 3) {
            issueB(W2, ch + 1, (ch + 1) & 1);
            CP_COMMIT;
            CP_WAIT1;
        } else {
            CP_WAIT0;
        }
        __syncthreads();
#pragma unroll
        for (int k16 = 0; k16 < 2; k16++) {
            int kg = ch * 32 + k16 * 16;
            int k0 = k16 * 16;
            unsigned a[4][4], b[4][2];
#pragma unroll
            for (int mt = 0; mt < 4; mt++)
                ldsm_x4(a[mt][0], a[mt][1], a[mt][2], a[mt][3],
                        actsB + (wm + mt * 16 + (lane & 15)) * 272
                              + (kg + ((lane >> 4) << 3)) * 2);
#pragma unroll
            for (int np = 0; np < 2; np++)
                ldsm_x4t(b[2 * np][0], b[2 * np][1], b[2 * np + 1][0], b[2 * np + 1][1],
                         bbufB[p] + (k0 + (lane & 7) + (lane & 8)) * 272
                                  + (wn + np * 16 + ((lane >> 4) << 3)) * 2);
#pragma unroll
            for (int mt = 0; mt < 4; mt++)
#pragma unroll
                for (int nt = 0; nt < 4; nt++) mma_bf16(d[mt][nt], a[mt], b[nt]);
        }
        __syncthreads();
    }

    issueB(W3, 0, 0);
    CP_COMMIT;

#pragma unroll
    for (int mt = 0; mt < 4; mt++)
#pragma unroll
        for (int nt = 0; nt < 4; nt++) {
            int row = wm + mt * 16 + lr;
            int col = wn + nt * 8 + 2 * lc;
            float2 bv = *(const float2*)&bn2[col];
            sActs[(row * 136 + col) >> 1] =
                pack_bf2(fmaxf(d[mt][nt][0] + bv.x, 0.f), fmaxf(d[mt][nt][1] + bv.y, 0.f));
            sActs[((row + 8) * 136 + col) >> 1] =
                pack_bf2(fmaxf(d[mt][nt][2] + bv.x, 0.f), fmaxf(d[mt][nt][3] + bv.y, 0.f));
        }

    // ===== GEMM3
#pragma unroll
    for (int mt = 0; mt < 4; mt++)
#pragma unroll
        for (int nt = 0; nt < 4; nt++)
#pragma unroll
            for (int i = 0; i < 4; i++) d[mt][nt][i] = 0.f;

    for (int ch = 0; ch < 4; ch++) {
        int p = ch & 1;
        if (ch < 3) {
            issueB(W3, ch + 1, (ch + 1) & 1);
            CP_COMMIT;
            CP_WAIT1;
        } else {
            CP_WAIT0;
        }
        __syncthreads();
#pragma unroll
        for (int k16 = 0; k16 < 2; k16++) {
            int kg = ch * 32 + k16 * 16;
            int k0 = k16 * 16;
            unsigned a[4][4], b[4][2];
#pragma unroll
            for (int mt = 0; mt < 4; mt++)
                ldsm_x4(a[mt][0], a[mt][1], a[mt][2], a[mt][3],
                        actsB + (wm + mt * 16 + (lane & 15)) * 272
                              + (kg + ((lane >> 4) << 3)) * 2);
#pragma unroll
            for (int np = 0; np < 2; np++)
                ldsm_x4t(b[2 * np][0], b[2 * np][1], b[2 * np + 1][0], b[2 * np + 1][1],
                         bbufB[p] + (k0 + (lane & 7) + (lane & 8)) * 272
                                  + (wn + np * 16 + ((lane >> 4) << 3)) * 2);
#pragma unroll
            for (int mt = 0; mt < 4; mt++)
#pragma unroll
                for (int nt = 0; nt < 4; nt++) mma_bf16(d[mt][nt], a[mt], b[nt]);
        }
        __syncthreads();
    }

    // epilogue3: bias + residual -> fp32 LN buffer (aliases acts/staging; all reads done)
#pragma unroll
    for (int mt = 0; mt < 4; mt++)
#pragma unroll
        for (int nt = 0; nt < 4; nt++) {
            int row = wm + mt * 16 + lr;
            int col = wn + nt * 8 + 2 * lc;
            float2 bv = *(const float2*)&bn3[col];
            int n0 = nb + row, n1 = nb + row + 8;
            float2 h0 = make_float2(0.f, 0.f), h1 = make_float2(0.f, 0.f);
            if (n0 < N_NODES) h0 = *(const float2*)&g_h[n0 * H + col];
            if (n1 < N_NODES) h1 = *(const float2*)&g_h[n1 * H + col];
            *(float2*)&sLN[row * 132 + col] =
                make_float2(h0.x + d[mt][nt][0] + bv.x, h0.y + d[mt][nt][1] + bv.y);
            *(float2*)&sLN[(row + 8) * 132 + col] =
                make_float2(h1.x + d[mt][nt][2] + bv.x, h1.y + d[mt][nt][3] + bv.y);
        }
    __syncthreads();

    // LayerNorm per row
    {
        for (int r = warp * 16; r < warp * 16 + 16; r++) {
            int node = nb + r;
            float v0 = sLN[r * 132 + lane];
            float v1 = sLN[r * 132 + lane + 32];
            float v2 = sLN[r * 132 + lane + 64];
            float v3 = sLN[r * 132 + lane + 96];
            float s = v0 + v1 + v2 + v3;
            float q = v0 * v0 + v1 * v1 + v2 * v2 + v3 * v3;
#pragma unroll
            for (int off = 16; off > 0; off >>= 1) {
                s += __shfl_xor_sync(0xffffffffu, s, off);
                q += __shfl_xor_sync(0xffffffffu, q, off);
            }
            float mean = s * (1.f / 128.f);
            float var = q * (1.f / 128.f) - mean * mean;
            float rstd = rsqrtf(var + 1e-5f);
            if (node < N_NODES) {
                float o0 = (v0 - mean) * rstd * lng[lane]      + lnb[lane];
                float o1 = (v1 - mean) * rstd * lng[lane + 32] + lnb[lane + 32];
                float o2 = (v2 - mean) * rstd * lng[lane + 64] + lnb[lane + 64];
                float o3 = (v3 - mean) * rstd * lng[lane + 96] + lnb[lane + 96];
                out[node * H + lane]      = o0;
                out[node * H + lane + 32] = o1;
                out[node * H + lane + 64] = o2;
                out[node * H + lane + 96] = o3;
                g_hb[node * H + lane]      = __float2bfloat16(o0);
                g_hb[node * H + lane + 32] = __float2bfloat16(o1);
                g_hb[node * H + lane + 64] = __float2bfloat16(o2);
                g_hb[node * H + lane + 96] = __float2bfloat16(o3);
            }
        }
    }
}

// ----------------------------------------------------------------
extern "C" void kernel_launch(void* const* d_in, const int* in_sizes, int n_in,
                              void* d_out, int out_size) {
    const float* x    = (const float*)d_in[0];
    const float* pos  = (const float*)d_in[1];
    const int*   ei   = (const int*)d_in[2];
    const float* W_in = (const float*)d_in[3];
    const float* b_in = (const float*)d_in[4];
    const float* We1  = (const float*)d_in[5];
    const float* be1  = (const float*)d_in[6];
    const float* We2  = (const float*)d_in[7];
    const float* be2  = (const float*)d_in[8];
    const float* We3  = (const float*)d_in[9];
    const float* be3  = (const float*)d_in[10];
    const float* Wn1  = (const float*)d_in[11];
    const float* bn1  = (const float*)d_in[12];
    const float* Wn2  = (const float*)d_in[13];
    const float* bn2  = (const float*)d_in[14];
    const float* Wn3  = (const float*)d_in[15];
    const float* bn3  = (const float*)d_in[16];
    const float* ln_g = (const float*)d_in[17];
    const float* ln_b = (const float*)d_in[18];

    const int* rowIdx = ei;
    const int* colIdx = ei + N_EDGES;

    cudaFuncSetAttribute(edge_kernel, cudaFuncAttributeMaxDynamicSharedMemorySize, SMEM_EDGE);
    cudaFuncSetAttribute(node_kernel, cudaFuncAttributeMaxDynamicSharedMemorySize, SMEM_NODE);

    float* hptr = nullptr;
    cudaGetSymbolAddress((void**)&hptr, g_h);

    int prep_total = LAYERS * KE_PAD * H + 2 * LAYERS * H * H
                   + LAYERS * KN * H + 2 * LAYERS * H * H;
    prep_weights<<<(prep_total + 255) / 256, 256>>>(We1, We2, We3, Wn1, Wn2, Wn3);
    embed_kernel<<<(N_NODES * H + 255) / 256, 256>>>(x, W_in, b_in);
    ea_kernel<<<(N_EDGES + 255) / 256, 256>>>(pos, rowIdx, colIdx);

    int edge_blocks = N_EDGES / BM;
    int node_blocks = (N_NODES + BM - 1) / BM;
    int zero_blocks = (N_NODES * H / 4) / 256;
    int cvt_blocks = (N_NODES * H / 8) / 256;

    for (int l = 0; l < LAYERS; l++) {
        zero_agg_kernel<<<zero_blocks, 256>>>();
        edge_kernel<<<edge_blocks, 256, SMEM_EDGE>>>(
            l, be1 + l * H, be2 + l * H, be3 + l * H, rowIdx, colIdx);
        cvt_agg_kernel<<<cvt_blocks, 256>>>();
        float* outp = (l == LAYERS - 1) ? (float*)d_out : hptr;
        node_kernel<<<node_blocks, 256, SMEM_NODE>>>(
            l, bn1 + l * H, bn2 + l * H, bn3 + l * H,
            ln_g + l * H, ln_b + l * H, outp);
    }
}